// round 5
// baseline (speedup 1.0000x reference)
#include <cuda_runtime.h>
#include <math.h>

#define BB 4
#define SS 1024
#define IN 1024
#define OUT 1024
#define NH 8
#define NE 16
#define PROJ 128
#define BT (BB*SS)        // 4096 tokens
#define RLEN (2*SS-1)     // 2047 relative positions

// ---------------- scratch (static device globals; allocation-free) ----------
__device__ float g_selval[BT*NH];
__device__ int   g_selidx[BT*NH];
__device__ int   g_cnt[NE];
__device__ int   g_list[NE*BT];
__device__ float g_k   [(size_t)BT*PROJ];
__device__ float g_v   [(size_t)BT*PROJ];
__device__ float g_pemb[(size_t)RLEN*IN];
__device__ float g_kpos[(size_t)RLEN*PROJ];
__device__ float g_q   [(size_t)BB*NH*SS*PROJ];
__device__ float g_P   [(size_t)BB*NH*SS*RLEN];   // band-only written
__device__ float g_z   [(size_t)BT*NE*PROJ];

// ---------------- tf32 helpers ---------------------------------------------
__device__ __forceinline__ float f2tf(float f) {
    unsigned r;
    asm("cvt.rna.tf32.f32 %0, %1;" : "=r"(r) : "f"(f));
    return __uint_as_float(r);
}

__device__ __forceinline__ void mma1688(float c[4],
                                        const float a[4], const float b[2]) {
    asm volatile(
        "mma.sync.aligned.m16n8k8.row.col.f32.tf32.tf32.f32 "
        "{%0,%1,%2,%3},{%4,%5,%6,%7},{%8,%9},{%0,%1,%2,%3};"
        : "+f"(c[0]), "+f"(c[1]), "+f"(c[2]), "+f"(c[3])
        : "r"(__float_as_uint(a[0])), "r"(__float_as_uint(a[1])),
          "r"(__float_as_uint(a[2])), "r"(__float_as_uint(a[3])),
          "r"(__float_as_uint(b[0])), "r"(__float_as_uint(b[1])));
}

// smem double-buffer geometry (dynamic)
#define AS_STRIDE 36
#define BS_STRIDE 136
#define AS_SZ (128*AS_STRIDE)          // per stage
#define BS_SZ (32*BS_STRIDE)
#define TG_SMEM ((2*(AS_SZ + BS_SZ))*4)
#define QX_SMEM (TG_SMEM + 128*4)

// ---------------- tf32 tensor-core GEMM, double-buffered, 2 CTA/SM ---------
// TRANSB=0: B row-major KxN (bmode 0 plain, 2 = out_proj expert blocks)
// TRANSB=1: B row-major NxK (A @ B^T). diagBand: n0 += 896 - m0.
// alphaMode: 0 none, 1 scale by sqrt(scale), 2 split-kv epilogue (k*sc | v)
template<int TRANSB>
__global__ __launch_bounds__(256, 2)
void tgemm(const float* __restrict__ A, const float* __restrict__ Bm,
           float* __restrict__ C,
           int M, int N, int K, int lda, int ldb, int ldc,
           int bmode, const float* __restrict__ scalep, int alphaMode,
           long sA, long sB, long sC, int bShiftB, int diagBand)
{
    extern __shared__ float dsm[];
    float* AsBase = dsm;
    float* BsBase = dsm + 2*AS_SZ;

    int bz = blockIdx.z;
    const float* Ap = A  + (long)bz * sA;
    const float* Bp = Bm + (long)(bz >> bShiftB) * sB;
    float*       Cp = C  + (long)bz * sC;
    int m0 = blockIdx.y * 128;
    int n0 = blockIdx.x * 128;
    if (diagBand) n0 += (896 - m0);

    int tid  = threadIdx.x;
    int wid  = tid >> 5, lane = tid & 31;
    int wm0  = (wid & 1) * 64;
    int wn0  = (wid >> 1) * 32;
    int lg   = lane >> 2;
    int lt   = lane & 3;

    float c[4][4][4];
    #pragma unroll
    for (int i = 0; i < 4; i++)
        #pragma unroll
        for (int j = 0; j < 4; j++)
            #pragma unroll
            for (int q = 0; q < 4; q++) c[i][j][q] = 0.f;

    float4 ra[4], rb[4];

    auto ldA = [&](int k0) {
        #pragma unroll
        for (int i = 0; i < 4; i++) {
            int m  = i * 32 + (tid >> 3);
            int kk = (tid & 7) * 4;
            ra[i] = make_float4(0.f, 0.f, 0.f, 0.f);
            if (m0 + m < M)
                ra[i] = *reinterpret_cast<const float4*>(Ap + (long)(m0 + m) * lda + k0 + kk);
        }
    };
    auto ldB = [&](int k0) {
        if (TRANSB == 0) {
            const float* bsrc;
            if (bmode == 0)      bsrc = Bp + (long)k0 * ldb + n0;
            else                 bsrc = Bp + (long)(k0 >> 7) * (PROJ * OUT) + (long)(k0 & 127) * OUT + n0;
            #pragma unroll
            for (int i = 0; i < 4; i++) {
                int kk = i * 8 + (tid >> 5);
                int nn = (tid & 31) * 4;
                rb[i] = *reinterpret_cast<const float4*>(bsrc + (long)kk * ldb + nn);
            }
        } else {
            #pragma unroll
            for (int i = 0; i < 4; i++) {
                int nn = i * 32 + (tid >> 3);
                int kk = (tid & 7) * 4;
                rb[i] = make_float4(0.f, 0.f, 0.f, 0.f);
                if (n0 + nn < N)
                    rb[i] = *reinterpret_cast<const float4*>(Bp + (long)(n0 + nn) * ldb + k0 + kk);
            }
        }
    };
    auto stAB = [&](int buf) {
        float* As = AsBase + buf * AS_SZ;
        float* Bs = BsBase + buf * BS_SZ;
        #pragma unroll
        for (int i = 0; i < 4; i++) {
            int m  = i * 32 + (tid >> 3);
            int kk = (tid & 7) * 4;
            float4 w = make_float4(f2tf(ra[i].x), f2tf(ra[i].y), f2tf(ra[i].z), f2tf(ra[i].w));
            *reinterpret_cast<float4*>(&As[m * AS_STRIDE + kk]) = w;
        }
        if (TRANSB == 0) {
            #pragma unroll
            for (int i = 0; i < 4; i++) {
                int kk = i * 8 + (tid >> 5);
                int nn = (tid & 31) * 4;
                float4 w = make_float4(f2tf(rb[i].x), f2tf(rb[i].y), f2tf(rb[i].z), f2tf(rb[i].w));
                *reinterpret_cast<float4*>(&Bs[kk * BS_STRIDE + nn]) = w;
            }
        } else {
            #pragma unroll
            for (int i = 0; i < 4; i++) {
                int nn = i * 32 + (tid >> 3);
                int kk = (tid & 7) * 4;
                Bs[(kk + 0) * BS_STRIDE + nn] = f2tf(rb[i].x);
                Bs[(kk + 1) * BS_STRIDE + nn] = f2tf(rb[i].y);
                Bs[(kk + 2) * BS_STRIDE + nn] = f2tf(rb[i].z);
                Bs[(kk + 3) * BS_STRIDE + nn] = f2tf(rb[i].w);
            }
        }
    };
    auto domma = [&](int buf) {
        float* As = AsBase + buf * AS_SZ;
        float* Bs = BsBase + buf * BS_SZ;
        #pragma unroll
        for (int ks = 0; ks < 4; ks++) {
            int kb = ks * 8;
            float a[4][4], b[4][2];
            #pragma unroll
            for (int mt = 0; mt < 4; mt++) {
                int r = wm0 + mt * 16 + lg;
                a[mt][0] = As[r * AS_STRIDE + kb + lt];
                a[mt][1] = As[(r + 8) * AS_STRIDE + kb + lt];
                a[mt][2] = As[r * AS_STRIDE + kb + 4 + lt];
                a[mt][3] = As[(r + 8) * AS_STRIDE + kb + 4 + lt];
            }
            #pragma unroll
            for (int nt = 0; nt < 4; nt++) {
                int cn = wn0 + nt * 8 + lg;
                b[nt][0] = Bs[(kb + lt) * BS_STRIDE + cn];
                b[nt][1] = Bs[(kb + 4 + lt) * BS_STRIDE + cn];
            }
            #pragma unroll
            for (int mt = 0; mt < 4; mt++)
                #pragma unroll
                for (int nt = 0; nt < 4; nt++)
                    mma1688(c[mt][nt], a[mt], b[nt]);
        }
    };

    int nk = K / 32;
    ldA(0); ldB(0);
    stAB(0);
    __syncthreads();
    for (int ki = 0; ki < nk; ki++) {
        if (ki + 1 < nk) { ldA((ki + 1) * 32); ldB((ki + 1) * 32); }
        domma(ki & 1);
        if (ki + 1 < nk) {
            stAB((ki + 1) & 1);
            __syncthreads();
        }
    }

    if (alphaMode == 2) {
        // kv split epilogue: col<128 -> g_k * sc ; col>=128 -> g_v
        float sc = sqrtf(scalep[0]);
        #pragma unroll
        for (int mt = 0; mt < 4; mt++) {
            #pragma unroll
            for (int nt = 0; nt < 4; nt++) {
                #pragma unroll
                for (int ri = 0; ri < 2; ri++) {
                    int r  = m0 + wm0 + mt * 16 + lg + ri * 8;
                    int cc = n0 + wn0 + nt * 8 + 2 * lt;
                    float v0 = c[mt][nt][ri * 2 + 0];
                    float v1 = c[mt][nt][ri * 2 + 1];
                    if (cc < PROJ) {
                        g_k[(size_t)r * PROJ + cc]     = sc * v0;
                        g_k[(size_t)r * PROJ + cc + 1] = sc * v1;
                    } else {
                        g_v[(size_t)r * PROJ + cc - PROJ]     = v0;
                        g_v[(size_t)r * PROJ + cc - PROJ + 1] = v1;
                    }
                }
            }
        }
        return;
    }

    float alpha = (alphaMode == 1) ? sqrtf(scalep[0]) : 1.f;
    #pragma unroll
    for (int mt = 0; mt < 4; mt++) {
        #pragma unroll
        for (int nt = 0; nt < 4; nt++) {
            int r  = m0 + wm0 + mt * 16 + lg;
            int cc = n0 + wn0 + nt * 8 + 2 * lt;
            if (r < M) {
                if (cc     < N) Cp[(long)r * ldc + cc]     = alpha * c[mt][nt][0];
                if (cc + 1 < N) Cp[(long)r * ldc + cc + 1] = alpha * c[mt][nt][1];
            }
            if (r + 8 < M) {
                if (cc     < N) Cp[(long)(r + 8) * ldc + cc]     = alpha * c[mt][nt][2];
                if (cc + 1 < N) Cp[(long)(r + 8) * ldc + cc + 1] = alpha * c[mt][nt][3];
            }
        }
    }
}

// ---------------- expert-bucketed q projection ------------------------------
__global__ __launch_bounds__(256, 2)
void qexp_kernel(const float* __restrict__ curr, const float* __restrict__ dtq,
                 const float* __restrict__ scalep)
{
    extern __shared__ float dsm[];
    float* AsBase = dsm;
    float* BsBase = dsm + 2*AS_SZ;
    int*   ent    = (int*)(dsm + 2*(AS_SZ + BS_SZ));

    int e   = blockIdx.z;
    int cnt = g_cnt[e];
    int t0  = blockIdx.y * 128;
    if (t0 >= cnt) return;

    int tid  = threadIdx.x;
    if (tid < 128)
        ent[tid] = (t0 + tid < cnt) ? g_list[e * BT + t0 + tid] : -1;
    __syncthreads();

    const float* Bp = dtq + (size_t)e * IN * PROJ;

    int wid  = tid >> 5, lane = tid & 31;
    int wm0  = (wid & 1) * 64;
    int wn0  = (wid >> 1) * 32;
    int lg   = lane >> 2;
    int lt   = lane & 3;

    int tok4[4];
    #pragma unroll
    for (int i = 0; i < 4; i++) {
        int m = i * 32 + (tid >> 3);
        int en = ent[m];
        tok4[i] = (en >= 0) ? (en >> 3) : -1;
    }

    float c[4][4][4];
    #pragma unroll
    for (int i = 0; i < 4; i++)
        #pragma unroll
        for (int j = 0; j < 4; j++)
            #pragma unroll
            for (int q = 0; q < 4; q++) c[i][j][q] = 0.f;

    float4 ra[4], rb[4];
    auto ldA = [&](int k0) {
        int kk = (tid & 7) * 4;
        #pragma unroll
        for (int i = 0; i < 4; i++) {
            ra[i] = make_float4(0.f, 0.f, 0.f, 0.f);
            if (tok4[i] >= 0)
                ra[i] = *reinterpret_cast<const float4*>(curr + (size_t)tok4[i] * IN + k0 + kk);
        }
    };
    auto ldB = [&](int k0) {
        const float* bsrc = Bp + (size_t)k0 * PROJ;
        #pragma unroll
        for (int i = 0; i < 4; i++) {
            int kk = i * 8 + (tid >> 5);
            int nn = (tid & 31) * 4;
            rb[i] = *reinterpret_cast<const float4*>(bsrc + (size_t)kk * PROJ + nn);
        }
    };
    auto stAB = [&](int buf) {
        float* As = AsBase + buf * AS_SZ;
        float* Bs = BsBase + buf * BS_SZ;
        int kk = (tid & 7) * 4;
        #pragma unroll
        for (int i = 0; i < 4; i++) {
            int m = i * 32 + (tid >> 3);
            float4 w = make_float4(f2tf(ra[i].x), f2tf(ra[i].y), f2tf(ra[i].z), f2tf(ra[i].w));
            *reinterpret_cast<float4*>(&As[m * AS_STRIDE + kk]) = w;
        }
        #pragma unroll
        for (int i = 0; i < 4; i++) {
            int kb = i * 8 + (tid >> 5);
            int nn = (tid & 31) * 4;
            float4 w = make_float4(f2tf(rb[i].x), f2tf(rb[i].y), f2tf(rb[i].z), f2tf(rb[i].w));
            *reinterpret_cast<float4*>(&Bs[kb * BS_STRIDE + nn]) = w;
        }
    };
    auto domma = [&](int buf) {
        float* As = AsBase + buf * AS_SZ;
        float* Bs = BsBase + buf * BS_SZ;
        #pragma unroll
        for (int ks = 0; ks < 4; ks++) {
            int kb = ks * 8;
            float a[4][4], b[4][2];
            #pragma unroll
            for (int mt = 0; mt < 4; mt++) {
                int r = wm0 + mt * 16 + lg;
                a[mt][0] = As[r * AS_STRIDE + kb + lt];
                a[mt][1] = As[(r + 8) * AS_STRIDE + kb + lt];
                a[mt][2] = As[r * AS_STRIDE + kb + 4 + lt];
                a[mt][3] = As[(r + 8) * AS_STRIDE + kb + 4 + lt];
            }
            #pragma unroll
            for (int nt = 0; nt < 4; nt++) {
                int cn = wn0 + nt * 8 + lg;
                b[nt][0] = Bs[(kb + lt) * BS_STRIDE + cn];
                b[nt][1] = Bs[(kb + 4 + lt) * BS_STRIDE + cn];
            }
            #pragma unroll
            for (int mt = 0; mt < 4; mt++)
                #pragma unroll
                for (int nt = 0; nt < 4; nt++)
                    mma1688(c[mt][nt], a[mt], b[nt]);
        }
    };

    ldA(0); ldB(0);
    stAB(0);
    __syncthreads();
    for (int ki = 0; ki < 32; ki++) {
        if (ki + 1 < 32) { ldA((ki + 1) * 32); ldB((ki + 1) * 32); }
        domma(ki & 1);
        if (ki + 1 < 32) { stAB((ki + 1) & 1); __syncthreads(); }
    }

    float alpha = sqrtf(scalep[0]);
    #pragma unroll
    for (int mt = 0; mt < 4; mt++) {
        #pragma unroll
        for (int ri = 0; ri < 2; ri++) {
            int rl = wm0 + mt * 16 + lg + ri * 8;
            int en = ent[rl];
            if (en < 0) continue;
            int token = en >> 3, h = en & 7;
            int b = token >> 10, s = token & 1023;
            float* dst = g_q + ((size_t)((b * NH + h) * SS + s)) * PROJ;
            #pragma unroll
            for (int nt = 0; nt < 4; nt++) {
                int cc = wn0 + nt * 8 + 2 * lt;
                dst[cc]     = alpha * c[mt][nt][ri * 2 + 0];
                dst[cc + 1] = alpha * c[mt][nt][ri * 2 + 1];
            }
        }
    }
}

// ---------------- bucket build ----------------------------------------------
__global__ void qbucket_kernel()
{
    int i = blockIdx.x * 256 + threadIdx.x;
    if (i >= BT * NH) return;
    int e = g_selidx[i];
    int pos = atomicAdd(&g_cnt[e], 1);
    g_list[e * BT + pos] = i;
}

// ---------------- fused flash attention -------------------------------------
__global__ __launch_bounds__(256)
void flash_kernel()
{
    extern __shared__ float sm[];
    float* Qs   = sm;                    // 64 x 132
    float* Ps   = Qs + 64 * 132;         // 64 x 132
    float* Kt   = Ps + 64 * 132;         // 128 x 132
    float* Vt   = Kt + 128 * 132;        // 128 x 136
    float* redm = Vt + 128 * 136;        // 64 x 4
    float* reds = redm + 256;            // 64 x 4

    int zh = blockIdx.y;
    int b  = zh >> 3, h = zh & 7;
    int s0 = blockIdx.x * 64;
    int tid = threadIdx.x;
    int wid = tid >> 5, lane = tid & 31;
    int lg = lane >> 2, lt = lane & 3;
    int wm0 = (wid & 1) * 32;
    int wn0 = (wid >> 1) * 32;

    {
        const float* qbase = g_q + (size_t)(zh * SS + s0) * PROJ;
        #pragma unroll
        for (int it = 0; it < 8; it++) {
            int lin = it * 256 + tid;
            int r = lin >> 5, cc = (lin & 31) * 4;
            float4 v = *reinterpret_cast<const float4*>(qbase + (size_t)r * PROJ + cc);
            float4 w = make_float4(f2tf(v.x), f2tf(v.y), f2tf(v.z), f2tf(v.w));
            *reinterpret_cast<float4*>(&Qs[r * 132 + cc]) = w;
        }
    }

    float o[2][4][4];
    float mrow[2][2], lrow[2][2];
    #pragma unroll
    for (int mt = 0; mt < 2; mt++) {
        mrow[mt][0] = mrow[mt][1] = -1e30f;
        lrow[mt][0] = lrow[mt][1] = 0.f;
        #pragma unroll
        for (int nt = 0; nt < 4; nt++)
            #pragma unroll
            for (int q = 0; q < 4; q++) o[mt][nt][q] = 0.f;
    }

    for (int kt = 0; kt < 8; kt++) {
        int t0  = kt * 128;
        int bt0 = b * SS + t0;
        #pragma unroll
        for (int it = 0; it < 16; it++) {
            int lin = it * 256 + tid;
            int r = lin >> 5, cc = (lin & 31) * 4;
            float4 kv4 = *reinterpret_cast<const float4*>(g_k + (size_t)(bt0 + r) * PROJ + cc);
            float4 vv4 = *reinterpret_cast<const float4*>(g_v + (size_t)(bt0 + r) * PROJ + cc);
            *reinterpret_cast<float4*>(&Kt[r * 132 + cc]) =
                make_float4(f2tf(kv4.x), f2tf(kv4.y), f2tf(kv4.z), f2tf(kv4.w));
            *reinterpret_cast<float4*>(&Vt[r * 136 + cc]) =
                make_float4(f2tf(vv4.x), f2tf(vv4.y), f2tf(vv4.z), f2tf(vv4.w));
        }
        __syncthreads();

        float s_[2][4][4];
        #pragma unroll
        for (int mt = 0; mt < 2; mt++)
            #pragma unroll
            for (int nt = 0; nt < 4; nt++)
                #pragma unroll
                for (int q = 0; q < 4; q++) s_[mt][nt][q] = 0.f;
        #pragma unroll
        for (int ks = 0; ks < 16; ks++) {
            int kb = ks * 8;
            float a[2][4], bf[4][2];
            #pragma unroll
            for (int mt = 0; mt < 2; mt++) {
                int r = wm0 + mt * 16 + lg;
                a[mt][0] = Qs[r * 132 + kb + lt];
                a[mt][1] = Qs[(r + 8) * 132 + kb + lt];
                a[mt][2] = Qs[r * 132 + kb + 4 + lt];
                a[mt][3] = Qs[(r + 8) * 132 + kb + 4 + lt];
            }
            #pragma unroll
            for (int nt = 0; nt < 4; nt++) {
                int cn = wn0 + nt * 8 + lg;
                bf[nt][0] = Kt[cn * 132 + kb + lt];
                bf[nt][1] = Kt[cn * 132 + kb + 4 + lt];
            }
            #pragma unroll
            for (int mt = 0; mt < 2; mt++)
                #pragma unroll
                for (int nt = 0; nt < 4; nt++)
                    mma1688(s_[mt][nt], a[mt], bf[nt]);
        }

        #pragma unroll
        for (int mt = 0; mt < 2; mt++) {
            #pragma unroll
            for (int ri = 0; ri < 2; ri++) {
                int srow = s0 + wm0 + mt * 16 + lg + ri * 8;
                const float* prow = g_P + (size_t)(zh * SS + srow) * RLEN + (1023 - srow) + t0;
                #pragma unroll
                for (int nt = 0; nt < 4; nt++) {
                    int c0 = wn0 + nt * 8 + 2 * lt;
                    s_[mt][nt][ri * 2 + 0] += prow[c0];
                    s_[mt][nt][ri * 2 + 1] += prow[c0 + 1];
                }
            }
        }

        #pragma unroll
        for (int mt = 0; mt < 2; mt++) {
            #pragma unroll
            for (int ri = 0; ri < 2; ri++) {
                float v = -1e30f;
                #pragma unroll
                for (int nt = 0; nt < 4; nt++)
                    v = fmaxf(v, fmaxf(s_[mt][nt][ri * 2], s_[mt][nt][ri * 2 + 1]));
                v = fmaxf(v, __shfl_xor_sync(0xffffffff, v, 1));
                v = fmaxf(v, __shfl_xor_sync(0xffffffff, v, 2));
                if (lt == 0) {
                    int rl = wm0 + mt * 16 + lg + ri * 8;
                    redm[rl * 4 + (wid >> 1)] = v;
                }
            }
        }
        __syncthreads();

        float scl[2][2];
        #pragma unroll
        for (int mt = 0; mt < 2; mt++) {
            #pragma unroll
            for (int ri = 0; ri < 2; ri++) {
                int rl = wm0 + mt * 16 + lg + ri * 8;
                float v = fmaxf(fmaxf(redm[rl * 4 + 0], redm[rl * 4 + 1]),
                                fmaxf(redm[rl * 4 + 2], redm[rl * 4 + 3]));
                float mnew = fmaxf(mrow[mt][ri], v);
                scl[mt][ri] = expf(mrow[mt][ri] - mnew);
                mrow[mt][ri] = mnew;
            }
        }

        #pragma unroll
        for (int mt = 0; mt < 2; mt++) {
            #pragma unroll
            for (int ri = 0; ri < 2; ri++) {
                float m = mrow[mt][ri];
                float sum = 0.f;
                int r = wm0 + mt * 16 + lg + ri * 8;
                #pragma unroll
                for (int nt = 0; nt < 4; nt++) {
                    float e0 = expf(s_[mt][nt][ri * 2 + 0] - m);
                    float e1 = expf(s_[mt][nt][ri * 2 + 1] - m);
                    s_[mt][nt][ri * 2 + 0] = e0;
                    s_[mt][nt][ri * 2 + 1] = e1;
                    sum += e0 + e1;
                    int c0 = wn0 + nt * 8 + 2 * lt;
                    Ps[r * 132 + c0]     = f2tf(e0);
                    Ps[r * 132 + c0 + 1] = f2tf(e1);
                    o[mt][nt][ri * 2 + 0] *= scl[mt][ri];
                    o[mt][nt][ri * 2 + 1] *= scl[mt][ri];
                }
                sum += __shfl_xor_sync(0xffffffff, sum, 1);
                sum += __shfl_xor_sync(0xffffffff, sum, 2);
                if (lt == 0) reds[r * 4 + (wid >> 1)] = sum;
            }
        }
        __syncthreads();

        #pragma unroll
        for (int mt = 0; mt < 2; mt++) {
            #pragma unroll
            for (int ri = 0; ri < 2; ri++) {
                int rl = wm0 + mt * 16 + lg + ri * 8;
                float ltile = reds[rl * 4 + 0] + reds[rl * 4 + 1]
                            + reds[rl * 4 + 2] + reds[rl * 4 + 3];
                lrow[mt][ri] = lrow[mt][ri] * scl[mt][ri] + ltile;
            }
        }

        #pragma unroll
        for (int ks = 0; ks < 16; ks++) {
            int kb = ks * 8;
            float a[2][4], bf[4][2];
            #pragma unroll
            for (int mt = 0; mt < 2; mt++) {
                int r = wm0 + mt * 16 + lg;
                a[mt][0] = Ps[r * 132 + kb + lt];
                a[mt][1] = Ps[(r + 8) * 132 + kb + lt];
                a[mt][2] = Ps[r * 132 + kb + 4 + lt];
                a[mt][3] = Ps[(r + 8) * 132 + kb + 4 + lt];
            }
            #pragma unroll
            for (int nt = 0; nt < 4; nt++) {
                int cn = wn0 + nt * 8 + lg;
                bf[nt][0] = Vt[(kb + lt) * 136 + cn];
                bf[nt][1] = Vt[(kb + 4 + lt) * 136 + cn];
            }
            #pragma unroll
            for (int mt = 0; mt < 2; mt++)
                #pragma unroll
                for (int nt = 0; nt < 4; nt++)
                    mma1688(o[mt][nt], a[mt], bf[nt]);
        }
        __syncthreads();
    }

    #pragma unroll
    for (int mt = 0; mt < 2; mt++) {
        #pragma unroll
        for (int ri = 0; ri < 2; ri++) {
            int sglob = s0 + wm0 + mt * 16 + lg + ri * 8;
            int token = b * SS + sglob;
            int   e = g_selidx[token * NH + h];
            float g = g_selval[token * NH + h];
            float inv = g / lrow[mt][ri];
            float* zrow = g_z + ((size_t)token * NE + e) * PROJ;
            #pragma unroll
            for (int nt = 0; nt < 4; nt++) {
                int c0 = wn0 + nt * 8 + 2 * lt;
                zrow[c0]     = o[mt][nt][ri * 2 + 0] * inv;
                zrow[c0 + 1] = o[mt][nt][ri * 2 + 1] * inv;
            }
        }
    }
}

// ---------------- sel = curr @ sel_dst^T, top-8, sigmoid --------------------
__global__ void sel_topk_kernel(const float* __restrict__ curr,
                                const float* __restrict__ sdst)
{
    __shared__ float srow[IN];
    __shared__ float wsum[NE][4];
    __shared__ float vals[NE];
    int bs = blockIdx.x;
    int tid = threadIdx.x;
    const float* row = curr + (long)bs * IN;
    for (int i = tid; i < IN; i += 128) srow[i] = row[i];
    __syncthreads();

    float acc[NE];
    #pragma unroll
    for (int e = 0; e < NE; e++) acc[e] = 0.f;
    for (int i = tid; i < IN; i += 128) {
        float c = srow[i];
        #pragma unroll
        for (int e = 0; e < NE; e++)
            acc[e] = fmaf(c, sdst[e*IN + i], acc[e]);
    }
    int lane = tid & 31, w = tid >> 5;
    #pragma unroll
    for (int e = 0; e < NE; e++) {
        float v = acc[e];
        #pragma unroll
        for (int o = 16; o > 0; o >>= 1) v += __shfl_xor_sync(0xffffffff, v, o);
        if (lane == 0) wsum[e][w] = v;
    }
    __syncthreads();
    if (tid < NE) vals[tid] = wsum[tid][0] + wsum[tid][1] + wsum[tid][2] + wsum[tid][3];
    __syncthreads();
    if (tid == 0) {
        bool used[NE];
        #pragma unroll
        for (int e = 0; e < NE; e++) used[e] = false;
        for (int h = 0; h < NH; h++) {
            int bi = 0; float bv = -3.4e38f;
            for (int e = 0; e < NE; e++)
                if (!used[e] && vals[e] > bv) { bv = vals[e]; bi = e; }
            used[bi] = true;
            g_selidx[bs*NH + h] = bi;
            g_selval[bs*NH + h] = 1.f / (1.f + expf(-bv));
        }
    }
}

// ---------------- sinusoidal embedding --------------------------------------
__global__ void pemb_kernel()
{
    int i = blockIdx.x;
    int tid = threadIdx.x;
    float pos = (float)i - (float)(SS - 1);
    float cst = -logf(10000.f) / (float)IN;
    for (int j = tid; j < IN/2; j += 256) {
        float dv = expf((float)(2*j) * cst);
        float s, co;
        sincosf(pos * dv, &s, &co);
        g_pemb[(long)i*IN + 2*j]     = s;
        g_pemb[(long)i*IN + 2*j + 1] = co;
    }
}

// ---------------- launch ----------------------------------------------------
static float* symf(const void* sym) { void* p = nullptr; cudaGetSymbolAddress(&p, sym); return (float*)p; }

extern "C" void kernel_launch(void* const* d_in, const int* in_sizes, int n_in,
                              void* d_out, int out_size)
{
    const float* curr  = (const float*)d_in[0];
    const float* attn  = (const float*)d_in[1];
    const float* dtq   = (const float*)d_in[2];
    const float* dtkv  = (const float*)d_in[3];
    const float* oproj = (const float*)d_in[4];
    const float* ptpk  = (const float*)d_in[5];
    const float* sdst  = (const float*)d_in[6];
    const float* scale = (const float*)d_in[7];
    float* out = (float*)d_out;

    float* p_pemb = symf(g_pemb);
    float* p_kpos = symf(g_kpos);
    float* p_q    = symf(g_q);
    float* p_P    = symf(g_P);
    float* p_z    = symf(g_z);
    float* p_cnt  = symf(g_cnt);

    static int smem_set = 0;
    const int FLASH_SMEM = (64*132 + 64*132 + 128*132 + 128*136 + 512) * 4;
    if (!smem_set) {
        cudaFuncSetAttribute(flash_kernel,
            cudaFuncAttributeMaxDynamicSharedMemorySize, FLASH_SMEM);
        cudaFuncSetAttribute(tgemm<0>,
            cudaFuncAttributeMaxDynamicSharedMemorySize, TG_SMEM);
        cudaFuncSetAttribute(tgemm<1>,
            cudaFuncAttributeMaxDynamicSharedMemorySize, TG_SMEM);
        cudaFuncSetAttribute(qexp_kernel,
            cudaFuncAttributeMaxDynamicSharedMemorySize, QX_SMEM);
        smem_set = 1;
    }

    // expert selection + buckets
    sel_topk_kernel<<<BT, 128>>>(curr, sdst);
    cudaMemsetAsync(p_cnt, 0, NE * sizeof(int));
    qbucket_kernel<<<(BT*NH + 255)/256, 256>>>();

    // bucketed q projection (writes g_q directly, scaled)
    qexp_kernel<<<dim3(1, 32, NE), 256, QX_SMEM>>>(curr, dtq, scale);

    // positional embedding + k_pos = pemb @ pos_to_pk^T * sc
    pemb_kernel<<<RLEN, 256>>>();
    tgemm<1><<<dim3(1, 16, 1), 256, TG_SMEM>>>(p_pemb, ptpk, p_kpos,
        RLEN, PROJ, IN, IN, IN, PROJ, 0, scale, 1, 0, 0, 0, 0, 0);

    // kv = attend_to @ data_to_kv, epilogue splits into g_k (*sc) and g_v
    tgemm<0><<<dim3(2, 32, 1), 256, TG_SMEM>>>(attn, dtkv, nullptr,
        BT, 2*PROJ, IN, IN, 2*PROJ, 2*PROJ, 0, scale, 2, 0, 0, 0, 0, 0);

    // P band = Q @ kpos^T  (only the diagonal band used by shift)
    tgemm<1><<<dim3(9, 8, BB*NH), 256, TG_SMEM>>>(p_q, p_kpos, p_P,
        SS, RLEN, PROJ, PROJ, PROJ, RLEN, 0, scale, 0,
        (long)SS*PROJ, 0, (long)SS*RLEN, 0, 1);

    // fused attention: QK^T + band, softmax, @V, gate, scatter into z
    cudaMemsetAsync(p_z, 0, (size_t)BT*NE*PROJ*sizeof(float));
    flash_kernel<<<dim3(16, BB*NH), 256, FLASH_SMEM>>>();

    // output projection
    tgemm<0><<<dim3(8, 32, 1), 256, TG_SMEM>>>(p_z, oproj, out,
        BT, OUT, NE*PROJ, NE*PROJ, OUT, OUT, 2, scale, 0, 0, 0, 0, 0, 0);
}

// round 7
// speedup vs baseline: 1.5165x; 1.5165x over previous
#include <cuda_runtime.h>
#include <cuda_fp16.h>
#include <math.h>

#define BB 4
#define SS 1024
#define IN 1024
#define OUT 1024
#define NH 8
#define NE 16
#define PROJ 128
#define BT (BB*SS)
#define RLEN (2*SS-1)

// ---------------- scratch ----------------------------------------------------
__device__ float g_selval[BT*NH];
__device__ int   g_selidx[BT*NH];
__device__ int   g_cnt[NE];
__device__ int   g_list[NE*BT];
__device__ float g_k   [(size_t)BT*PROJ];
__device__ float g_v   [(size_t)BT*PROJ];
__device__ float g_pemb[(size_t)RLEN*IN];
__device__ float g_kpos[(size_t)RLEN*PROJ];
__device__ float g_q   [(size_t)BB*NH*SS*PROJ];
__device__ float g_P   [(size_t)BB*NH*SS*RLEN];
__device__ float g_z   [(size_t)BT*NE*PROJ];

// ---------------- fp16 helpers ----------------------------------------------
__device__ __forceinline__ unsigned pk2(float x, float y) {
    __half2 h = __floats2half2_rn(x, y);
    return *reinterpret_cast<unsigned*>(&h);
}
__device__ __forceinline__ void mmaf16(float c[4], const unsigned a[4],
                                       const unsigned b[2]) {
    asm volatile(
        "mma.sync.aligned.m16n8k16.row.col.f32.f16.f16.f32 "
        "{%0,%1,%2,%3},{%4,%5,%6,%7},{%8,%9},{%0,%1,%2,%3};"
        : "+f"(c[0]), "+f"(c[1]), "+f"(c[2]), "+f"(c[3])
        : "r"(a[0]), "r"(a[1]), "r"(a[2]), "r"(a[3]),
          "r"(b[0]), "r"(b[1]));
}

// tile geometry: 128x128 C tile, K_TILE=32, fp16 tiles K-contiguous, stride 40
#define TW 40
#define STG_H (128*TW)                  // halves per stage (A or B)
#define TG_SMEM (4*STG_H*2)             // 2 stages x (A+B) in bytes = 40960
#define QX_SMEM (TG_SMEM + 128*4)

// ---------------- fp16 tensor GEMM, double-buffered ------------------------
// TRANSB=0: B row-major KxN (bmode 0 plain, 2 = out_proj expert blocks)
// TRANSB=1: B row-major NxK (A @ B^T). diagBand: n0 += 896 - m0.
// alphaMode: 0 none, 1 *sqrt(scale), 2 split-kv epilogue (k*sc | v)
template<int TRANSB>
__global__ __launch_bounds__(256, 2)
void tgemm(const float* __restrict__ A, const float* __restrict__ Bm,
           float* __restrict__ C,
           int M, int N, int K, int lda, int ldb, int ldc,
           int bmode, const float* __restrict__ scalep, int alphaMode,
           long sA, long sB, long sC, int bShiftB, int diagBand)
{
    extern __shared__ half hsm[];
    half* AsBase = hsm;                  // 2 stages of 128 x TW
    half* BsBase = hsm + 2*STG_H;        // 2 stages of 128 x TW (rows = n)

    int bz = blockIdx.z;
    const float* Ap = A  + (long)bz * sA;
    const float* Bp = Bm + (long)(bz >> bShiftB) * sB;
    float*       Cp = C  + (long)bz * sC;
    int m0 = blockIdx.y * 128;
    int n0 = blockIdx.x * 128;
    if (diagBand) n0 += (896 - m0);

    int tid  = threadIdx.x;
    int wid  = tid >> 5, lane = tid & 31;
    int wm0  = (wid & 1) * 64;
    int wn0  = (wid >> 1) * 32;
    int lg   = lane >> 2;
    int lt   = lane & 3;

    float c[4][4][4];
    #pragma unroll
    for (int i = 0; i < 4; i++)
        #pragma unroll
        for (int j = 0; j < 4; j++)
            #pragma unroll
            for (int q = 0; q < 4; q++) c[i][j][q] = 0.f;

    float4 ra[4];
    float4 rb4[4];     // TRANSB=1 path
    float  cv[16];     // TRANSB=0 path

    auto ldA = [&](int k0) {
        #pragma unroll
        for (int i = 0; i < 4; i++) {
            int m  = i * 32 + (tid >> 3);
            int kk = (tid & 7) * 4;
            ra[i] = make_float4(0.f, 0.f, 0.f, 0.f);
            if (m0 + m < M)
                ra[i] = *reinterpret_cast<const float4*>(Ap + (long)(m0 + m) * lda + k0 + kk);
        }
    };
    auto ldB = [&](int k0) {
        if (TRANSB == 0) {
            int n    = tid & 127;
            int kseg = (tid >> 7) * 16;
            const float* src;
            long stride;
            if (bmode == 0) {
                src = Bp + (long)(k0 + kseg) * ldb + n0 + n;
                stride = ldb;
            } else {
                int kg = k0 + kseg;
                src = Bp + (long)(kg >> 7) * (PROJ * OUT) + (long)(kg & 127) * OUT + n0 + n;
                stride = OUT;
            }
            #pragma unroll
            for (int j = 0; j < 16; j++) cv[j] = src[(long)j * stride];
        } else {
            #pragma unroll
            for (int i = 0; i < 4; i++) {
                int nn = i * 32 + (tid >> 3);
                int kk = (tid & 7) * 4;
                rb4[i] = make_float4(0.f, 0.f, 0.f, 0.f);
                if (n0 + nn < N)
                    rb4[i] = *reinterpret_cast<const float4*>(Bp + (long)(n0 + nn) * ldb + k0 + kk);
            }
        }
    };
    auto stAB = [&](int buf) {
        half* As = AsBase + buf * STG_H;
        half* Bs = BsBase + buf * STG_H;
        #pragma unroll
        for (int i = 0; i < 4; i++) {
            int m  = i * 32 + (tid >> 3);
            int kk = (tid & 7) * 4;
            uint2 w;
            w.x = pk2(ra[i].x, ra[i].y);
            w.y = pk2(ra[i].z, ra[i].w);
            *reinterpret_cast<uint2*>(&As[m * TW + kk]) = w;
        }
        if (TRANSB == 0) {
            int n    = tid & 127;
            int kseg = (tid >> 7) * 16;
            #pragma unroll
            for (int j2 = 0; j2 < 4; j2++) {
                uint2 w;
                w.x = pk2(cv[j2*4+0], cv[j2*4+1]);
                w.y = pk2(cv[j2*4+2], cv[j2*4+3]);
                *reinterpret_cast<uint2*>(&Bs[n * TW + kseg + j2*4]) = w;
            }
        } else {
            #pragma unroll
            for (int i = 0; i < 4; i++) {
                int nn = i * 32 + (tid >> 3);
                int kk = (tid & 7) * 4;
                uint2 w;
                w.x = pk2(rb4[i].x, rb4[i].y);
                w.y = pk2(rb4[i].z, rb4[i].w);
                *reinterpret_cast<uint2*>(&Bs[nn * TW + kk]) = w;
            }
        }
    };
    auto domma = [&](int buf) {
        half* As = AsBase + buf * STG_H;
        half* Bs = BsBase + buf * STG_H;
        #pragma unroll
        for (int ks = 0; ks < 2; ks++) {
            int kb = ks * 16;
            unsigned a[4][4], b[4][2];
            #pragma unroll
            for (int mt = 0; mt < 4; mt++) {
                int r = wm0 + mt * 16 + lg;
                a[mt][0] = *reinterpret_cast<unsigned*>(&As[r * TW + kb + 2*lt]);
                a[mt][1] = *reinterpret_cast<unsigned*>(&As[(r + 8) * TW + kb + 2*lt]);
                a[mt][2] = *reinterpret_cast<unsigned*>(&As[r * TW + kb + 2*lt + 8]);
                a[mt][3] = *reinterpret_cast<unsigned*>(&As[(r + 8) * TW + kb + 2*lt + 8]);
            }
            #pragma unroll
            for (int nt = 0; nt < 4; nt++) {
                int cn = wn0 + nt * 8 + lg;
                b[nt][0] = *reinterpret_cast<unsigned*>(&Bs[cn * TW + kb + 2*lt]);
                b[nt][1] = *reinterpret_cast<unsigned*>(&Bs[cn * TW + kb + 2*lt + 8]);
            }
            #pragma unroll
            for (int mt = 0; mt < 4; mt++)
                #pragma unroll
                for (int nt = 0; nt < 4; nt++)
                    mmaf16(c[mt][nt], a[mt], b[nt]);
        }
    };

    int nk = K / 32;
    ldA(0); ldB(0);
    stAB(0);
    __syncthreads();
    for (int ki = 0; ki < nk; ki++) {
        if (ki + 1 < nk) { ldA((ki + 1) * 32); ldB((ki + 1) * 32); }
        domma(ki & 1);
        if (ki + 1 < nk) {
            stAB((ki + 1) & 1);
            __syncthreads();
        }
    }

    if (alphaMode == 2) {
        float sc = sqrtf(scalep[0]);
        #pragma unroll
        for (int mt = 0; mt < 4; mt++) {
            #pragma unroll
            for (int nt = 0; nt < 4; nt++) {
                #pragma unroll
                for (int ri = 0; ri < 2; ri++) {
                    int r  = m0 + wm0 + mt * 16 + lg + ri * 8;
                    int cc = n0 + wn0 + nt * 8 + 2 * lt;
                    float v0 = c[mt][nt][ri * 2 + 0];
                    float v1 = c[mt][nt][ri * 2 + 1];
                    if (cc < PROJ) {
                        g_k[(size_t)r * PROJ + cc]     = sc * v0;
                        g_k[(size_t)r * PROJ + cc + 1] = sc * v1;
                    } else {
                        g_v[(size_t)r * PROJ + cc - PROJ]     = v0;
                        g_v[(size_t)r * PROJ + cc - PROJ + 1] = v1;
                    }
                }
            }
        }
        return;
    }

    float alpha = (alphaMode == 1) ? sqrtf(scalep[0]) : 1.f;
    #pragma unroll
    for (int mt = 0; mt < 4; mt++) {
        #pragma unroll
        for (int nt = 0; nt < 4; nt++) {
            int r  = m0 + wm0 + mt * 16 + lg;
            int cc = n0 + wn0 + nt * 8 + 2 * lt;
            if (r < M) {
                if (cc     < N) Cp[(long)r * ldc + cc]     = alpha * c[mt][nt][0];
                if (cc + 1 < N) Cp[(long)r * ldc + cc + 1] = alpha * c[mt][nt][1];
            }
            if (r + 8 < M) {
                if (cc     < N) Cp[(long)(r + 8) * ldc + cc]     = alpha * c[mt][nt][2];
                if (cc + 1 < N) Cp[(long)(r + 8) * ldc + cc + 1] = alpha * c[mt][nt][3];
            }
        }
    }
}

// ---------------- expert-bucketed q projection (fp16 MMA) -------------------
__global__ __launch_bounds__(256, 2)
void qexp_kernel(const float* __restrict__ curr, const float* __restrict__ dtq,
                 const float* __restrict__ scalep)
{
    extern __shared__ half hsm[];
    half* AsBase = hsm;
    half* BsBase = hsm + 2*STG_H;
    int*  ent    = (int*)(hsm + 4*STG_H);

    int e   = blockIdx.z;
    int cnt = g_cnt[e];
    int t0  = blockIdx.y * 128;
    if (t0 >= cnt) return;

    int tid  = threadIdx.x;
    if (tid < 128)
        ent[tid] = (t0 + tid < cnt) ? g_list[e * BT + t0 + tid] : -1;
    __syncthreads();

    const float* Bp = dtq + (size_t)e * IN * PROJ;

    int wid  = tid >> 5, lane = tid & 31;
    int wm0  = (wid & 1) * 64;
    int wn0  = (wid >> 1) * 32;
    int lg   = lane >> 2;
    int lt   = lane & 3;

    int tok4[4];
    #pragma unroll
    for (int i = 0; i < 4; i++) {
        int m = i * 32 + (tid >> 3);
        int en = ent[m];
        tok4[i] = (en >= 0) ? (en >> 3) : -1;
    }

    float c[4][4][4];
    #pragma unroll
    for (int i = 0; i < 4; i++)
        #pragma unroll
        for (int j = 0; j < 4; j++)
            #pragma unroll
            for (int q = 0; q < 4; q++) c[i][j][q] = 0.f;

    float4 ra[4];
    float  cv[16];
    auto ldA = [&](int k0) {
        int kk = (tid & 7) * 4;
        #pragma unroll
        for (int i = 0; i < 4; i++) {
            ra[i] = make_float4(0.f, 0.f, 0.f, 0.f);
            if (tok4[i] >= 0)
                ra[i] = *reinterpret_cast<const float4*>(curr + (size_t)tok4[i] * IN + k0 + kk);
        }
    };
    auto ldB = [&](int k0) {
        int n    = tid & 127;
        int kseg = (tid >> 7) * 16;
        const float* src = Bp + (size_t)(k0 + kseg) * PROJ + n;
        #pragma unroll
        for (int j = 0; j < 16; j++) cv[j] = src[(size_t)j * PROJ];
    };
    auto stAB = [&](int buf) {
        half* As = AsBase + buf * STG_H;
        half* Bs = BsBase + buf * STG_H;
        int kk = (tid & 7) * 4;
        #pragma unroll
        for (int i = 0; i < 4; i++) {
            int m = i * 32 + (tid >> 3);
            uint2 w;
            w.x = pk2(ra[i].x, ra[i].y);
            w.y = pk2(ra[i].z, ra[i].w);
            *reinterpret_cast<uint2*>(&As[m * TW + kk]) = w;
        }
        int n    = tid & 127;
        int kseg = (tid >> 7) * 16;
        #pragma unroll
        for (int j2 = 0; j2 < 4; j2++) {
            uint2 w;
            w.x = pk2(cv[j2*4+0], cv[j2*4+1]);
            w.y = pk2(cv[j2*4+2], cv[j2*4+3]);
            *reinterpret_cast<uint2*>(&Bs[n * TW + kseg + j2*4]) = w;
        }
    };
    auto domma = [&](int buf) {
        half* As = AsBase + buf * STG_H;
        half* Bs = BsBase + buf * STG_H;
        #pragma unroll
        for (int ks = 0; ks < 2; ks++) {
            int kb = ks * 16;
            unsigned a[4][4], b[4][2];
            #pragma unroll
            for (int mt = 0; mt < 4; mt++) {
                int r = wm0 + mt * 16 + lg;
                a[mt][0] = *reinterpret_cast<unsigned*>(&As[r * TW + kb + 2*lt]);
                a[mt][1] = *reinterpret_cast<unsigned*>(&As[(r + 8) * TW + kb + 2*lt]);
                a[mt][2] = *reinterpret_cast<unsigned*>(&As[r * TW + kb + 2*lt + 8]);
                a[mt][3] = *reinterpret_cast<unsigned*>(&As[(r + 8) * TW + kb + 2*lt + 8]);
            }
            #pragma unroll
            for (int nt = 0; nt < 4; nt++) {
                int cn = wn0 + nt * 8 + lg;
                b[nt][0] = *reinterpret_cast<unsigned*>(&Bs[cn * TW + kb + 2*lt]);
                b[nt][1] = *reinterpret_cast<unsigned*>(&Bs[cn * TW + kb + 2*lt + 8]);
            }
            #pragma unroll
            for (int mt = 0; mt < 4; mt++)
                #pragma unroll
                for (int nt = 0; nt < 4; nt++)
                    mmaf16(c[mt][nt], a[mt], b[nt]);
        }
    };

    ldA(0); ldB(0);
    stAB(0);
    __syncthreads();
    for (int ki = 0; ki < 32; ki++) {
        if (ki + 1 < 32) { ldA((ki + 1) * 32); ldB((ki + 1) * 32); }
        domma(ki & 1);
        if (ki + 1 < 32) { stAB((ki + 1) & 1); __syncthreads(); }
    }

    float alpha = sqrtf(scalep[0]);
    #pragma unroll
    for (int mt = 0; mt < 4; mt++) {
        #pragma unroll
        for (int ri = 0; ri < 2; ri++) {
            int rl = wm0 + mt * 16 + lg + ri * 8;
            int en = ent[rl];
            if (en < 0) continue;
            int token = en >> 3, h = en & 7;
            int b = token >> 10, s = token & 1023;
            float* dst = g_q + ((size_t)((b * NH + h) * SS + s)) * PROJ;
            #pragma unroll
            for (int nt = 0; nt < 4; nt++) {
                int cc = wn0 + nt * 8 + 2 * lt;
                dst[cc]     = alpha * c[mt][nt][ri * 2 + 0];
                dst[cc + 1] = alpha * c[mt][nt][ri * 2 + 1];
            }
        }
    }
}

// ---------------- bucket build ----------------------------------------------
__global__ void qbucket_kernel()
{
    int i = blockIdx.x * 256 + threadIdx.x;
    if (i >= BT * NH) return;
    int e = g_selidx[i];
    int pos = atomicAdd(&g_cnt[e], 1);
    g_list[e * BT + pos] = i;
}

// ---------------- fused flash attention (fp16 MMA) ---------------------------
#define FQW 136
__global__ __launch_bounds__(256)
void flash_kernel()
{
    extern __shared__ char smc[];
    half* Qs = (half*)smc;                           // 64 x 136
    half* Ps = Qs + 64*FQW;                          // 64 x 136
    half* Kt = Ps + 64*FQW;                          // 128 x 136
    unsigned* Vt2 = (unsigned*)(Kt + 128*FQW);       // 64 x 136 (paired V)
    float* redm = (float*)(Vt2 + 64*FQW);            // 256
    float* reds = redm + 256;                        // 256

    int zh = blockIdx.y;
    int b  = zh >> 3, h = zh & 7;
    int s0 = blockIdx.x * 64;
    int tid = threadIdx.x;
    int wid = tid >> 5, lane = tid & 31;
    int lg = lane >> 2, lt = lane & 3;
    int wm0 = (wid & 1) * 32;
    int wn0 = (wid >> 1) * 32;

    // Q tile 64x128 -> half
    {
        const float* qbase = g_q + (size_t)(zh * SS + s0) * PROJ;
        #pragma unroll
        for (int it = 0; it < 8; it++) {
            int lin = it * 256 + tid;
            int r = lin >> 5, cc = (lin & 31) * 4;
            float4 v = *reinterpret_cast<const float4*>(qbase + (size_t)r * PROJ + cc);
            uint2 w; w.x = pk2(v.x, v.y); w.y = pk2(v.z, v.w);
            *reinterpret_cast<uint2*>(&Qs[r * FQW + cc]) = w;
        }
    }

    float o[2][4][4];
    float mrow[2][2], lrow[2][2];
    #pragma unroll
    for (int mt = 0; mt < 2; mt++) {
        mrow[mt][0] = mrow[mt][1] = -1e30f;
        lrow[mt][0] = lrow[mt][1] = 0.f;
        #pragma unroll
        for (int nt = 0; nt < 4; nt++)
            #pragma unroll
            for (int q = 0; q < 4; q++) o[mt][nt][q] = 0.f;
    }

    for (int kt = 0; kt < 8; kt++) {
        int t0  = kt * 128;
        int bt0 = b * SS + t0;
        // K tile 128x128 -> half [t][p]
        #pragma unroll
        for (int it = 0; it < 16; it++) {
            int lin = it * 256 + tid;
            int r = lin >> 5, cc = (lin & 31) * 4;
            float4 kv4 = *reinterpret_cast<const float4*>(g_k + (size_t)(bt0 + r) * PROJ + cc);
            uint2 w; w.x = pk2(kv4.x, kv4.y); w.y = pk2(kv4.z, kv4.w);
            *reinterpret_cast<uint2*>(&Kt[r * FQW + cc]) = w;
        }
        // V tile paired: Vt2[t/2][p] = {V[2t'][p], V[2t'+1][p]}
        #pragma unroll
        for (int it = 0; it < 8; it++) {
            int lin = it * 256 + tid;
            int tp = lin >> 5, p0 = (lin & 31) * 4;
            float4 v0 = *reinterpret_cast<const float4*>(g_v + (size_t)(bt0 + 2*tp) * PROJ + p0);
            float4 v1 = *reinterpret_cast<const float4*>(g_v + (size_t)(bt0 + 2*tp + 1) * PROJ + p0);
            uint4 w;
            w.x = pk2(v0.x, v1.x); w.y = pk2(v0.y, v1.y);
            w.z = pk2(v0.z, v1.z); w.w = pk2(v0.w, v1.w);
            *reinterpret_cast<uint4*>(&Vt2[tp * FQW + p0]) = w;
        }
        __syncthreads();

        // S = Q K^T  (k = PROJ = 128, 8 fp16 k-steps)
        float s_[2][4][4];
        #pragma unroll
        for (int mt = 0; mt < 2; mt++)
            #pragma unroll
            for (int nt = 0; nt < 4; nt++)
                #pragma unroll
                for (int q = 0; q < 4; q++) s_[mt][nt][q] = 0.f;
        #pragma unroll
        for (int ks = 0; ks < 8; ks++) {
            int kb = ks * 16;
            unsigned a[2][4], bf[4][2];
            #pragma unroll
            for (int mt = 0; mt < 2; mt++) {
                int r = wm0 + mt * 16 + lg;
                a[mt][0] = *reinterpret_cast<unsigned*>(&Qs[r * FQW + kb + 2*lt]);
                a[mt][1] = *reinterpret_cast<unsigned*>(&Qs[(r + 8) * FQW + kb + 2*lt]);
                a[mt][2] = *reinterpret_cast<unsigned*>(&Qs[r * FQW + kb + 2*lt + 8]);
                a[mt][3] = *reinterpret_cast<unsigned*>(&Qs[(r + 8) * FQW + kb + 2*lt + 8]);
            }
            #pragma unroll
            for (int nt = 0; nt < 4; nt++) {
                int cn = wn0 + nt * 8 + lg;
                bf[nt][0] = *reinterpret_cast<unsigned*>(&Kt[cn * FQW + kb + 2*lt]);
                bf[nt][1] = *reinterpret_cast<unsigned*>(&Kt[cn * FQW + kb + 2*lt + 8]);
            }
            #pragma unroll
            for (int mt = 0; mt < 2; mt++)
                #pragma unroll
                for (int nt = 0; nt < 4; nt++)
                    mmaf16(s_[mt][nt], a[mt], bf[nt]);
        }

        // add relative-position band from g_P
        #pragma unroll
        for (int mt = 0; mt < 2; mt++) {
            #pragma unroll
            for (int ri = 0; ri < 2; ri++) {
                int srow = s0 + wm0 + mt * 16 + lg + ri * 8;
                const float* prow = g_P + (size_t)(zh * SS + srow) * RLEN + (1023 - srow) + t0;
                #pragma unroll
                for (int nt = 0; nt < 4; nt++) {
                    int c0 = wn0 + nt * 8 + 2 * lt;
                    s_[mt][nt][ri * 2 + 0] += prow[c0];
                    s_[mt][nt][ri * 2 + 1] += prow[c0 + 1];
                }
            }
        }

        // row max
        #pragma unroll
        for (int mt = 0; mt < 2; mt++) {
            #pragma unroll
            for (int ri = 0; ri < 2; ri++) {
                float v = -1e30f;
                #pragma unroll
                for (int nt = 0; nt < 4; nt++)
                    v = fmaxf(v, fmaxf(s_[mt][nt][ri * 2], s_[mt][nt][ri * 2 + 1]));
                v = fmaxf(v, __shfl_xor_sync(0xffffffff, v, 1));
                v = fmaxf(v, __shfl_xor_sync(0xffffffff, v, 2));
                if (lt == 0) {
                    int rl = wm0 + mt * 16 + lg + ri * 8;
                    redm[rl * 4 + (wid >> 1)] = v;
                }
            }
        }
        __syncthreads();

        float scl[2][2];
        #pragma unroll
        for (int mt = 0; mt < 2; mt++) {
            #pragma unroll
            for (int ri = 0; ri < 2; ri++) {
                int rl = wm0 + mt * 16 + lg + ri * 8;
                float v = fmaxf(fmaxf(redm[rl * 4 + 0], redm[rl * 4 + 1]),
                                fmaxf(redm[rl * 4 + 2], redm[rl * 4 + 3]));
                float mnew = fmaxf(mrow[mt][ri], v);
                scl[mt][ri] = expf(mrow[mt][ri] - mnew);
                mrow[mt][ri] = mnew;
            }
        }

        // exp, partial sums, rescale O, stage probs to Ps (fp16)
        #pragma unroll
        for (int mt = 0; mt < 2; mt++) {
            #pragma unroll
            for (int ri = 0; ri < 2; ri++) {
                float m = mrow[mt][ri];
                float sum = 0.f;
                int r = wm0 + mt * 16 + lg + ri * 8;
                #pragma unroll
                for (int nt = 0; nt < 4; nt++) {
                    float e0 = expf(s_[mt][nt][ri * 2 + 0] - m);
                    float e1 = expf(s_[mt][nt][ri * 2 + 1] - m);
                    sum += e0 + e1;
                    int c0 = wn0 + nt * 8 + 2 * lt;
                    *reinterpret_cast<unsigned*>(&Ps[r * FQW + c0]) = pk2(e0, e1);
                    o[mt][nt][ri * 2 + 0] *= scl[mt][ri];
                    o[mt][nt][ri * 2 + 1] *= scl[mt][ri];
                }
                sum += __shfl_xor_sync(0xffffffff, sum, 1);
                sum += __shfl_xor_sync(0xffffffff, sum, 2);
                if (lt == 0) reds[r * 4 + (wid >> 1)] = sum;
            }
        }
        __syncthreads();

        #pragma unroll
        for (int mt = 0; mt < 2; mt++) {
            #pragma unroll
            for (int ri = 0; ri < 2; ri++) {
                int rl = wm0 + mt * 16 + lg + ri * 8;
                float ltile = reds[rl * 4 + 0] + reds[rl * 4 + 1]
                            + reds[rl * 4 + 2] + reds[rl * 4 + 3];
                lrow[mt][ri] = lrow[mt][ri] * scl[mt][ri] + ltile;
            }
        }

        // O += P @ V  (k = t = 128, 8 fp16 k-steps, B from paired Vt2)
        #pragma unroll
        for (int ks = 0; ks < 8; ks++) {
            int kb = ks * 16;
            unsigned a[2][4], bf[4][2];
            #pragma unroll
            for (int mt = 0; mt < 2; mt++) {
                int r = wm0 + mt * 16 + lg;
                a[mt][0] = *reinterpret_cast<unsigned*>(&Ps[r * FQW + kb + 2*lt]);
                a[mt][1] = *reinterpret_cast<unsigned*>(&Ps[(r + 8) * FQW + kb + 2*lt]);
                a[mt][2] = *reinterpret_cast<unsigned*>(&Ps[r * FQW + kb + 2*lt + 8]);
                a[mt][3] = *reinterpret_cast<unsigned*>(&Ps[(r + 8) * FQW + kb + 2*lt + 8]);
            }
            #pragma unroll
            for (int nt = 0; nt < 4; nt++) {
                int col = wn0 + nt * 8 + lg;
                bf[nt][0] = Vt2[(kb/2 + lt) * FQW + col];
                bf[nt][1] = Vt2[(kb/2 + lt + 4) * FQW + col];
            }
            #pragma unroll
            for (int mt = 0; mt < 2; mt++)
                #pragma unroll
                for (int nt = 0; nt < 4; nt++)
                    mmaf16(o[mt][nt], a[mt], bf[nt]);
        }
        __syncthreads();
    }

    // epilogue: normalize, gate, scatter into z
    #pragma unroll
    for (int mt = 0; mt < 2; mt++) {
        #pragma unroll
        for (int ri = 0; ri < 2; ri++) {
            int sglob = s0 + wm0 + mt * 16 + lg + ri * 8;
            int token = b * SS + sglob;
            int   e = g_selidx[token * NH + h];
            float g = g_selval[token * NH + h];
            float inv = g / lrow[mt][ri];
            float* zrow = g_z + ((size_t)token * NE + e) * PROJ;
            #pragma unroll
            for (int nt = 0; nt < 4; nt++) {
                int c0 = wn0 + nt * 8 + 2 * lt;
                zrow[c0]     = o[mt][nt][ri * 2 + 0] * inv;
                zrow[c0 + 1] = o[mt][nt][ri * 2 + 1] * inv;
            }
        }
    }
}

// ---------------- sel = curr @ sel_dst^T, top-8, sigmoid --------------------
__global__ void sel_topk_kernel(const float* __restrict__ curr,
                                const float* __restrict__ sdst)
{
    __shared__ float srow[IN];
    __shared__ float wsum[NE][4];
    __shared__ float vals[NE];
    int bs = blockIdx.x;
    int tid = threadIdx.x;
    const float* row = curr + (long)bs * IN;
    for (int i = tid; i < IN; i += 128) srow[i] = row[i];
    __syncthreads();

    float acc[NE];
    #pragma unroll
    for (int e = 0; e < NE; e++) acc[e] = 0.f;
    for (int i = tid; i < IN; i += 128) {
        float c = srow[i];
        #pragma unroll
        for (int e = 0; e < NE; e++)
            acc[e] = fmaf(c, sdst[e*IN + i], acc[e]);
    }
    int lane = tid & 31, w = tid >> 5;
    #pragma unroll
    for (int e = 0; e < NE; e++) {
        float v = acc[e];
        #pragma unroll
        for (int o = 16; o > 0; o >>= 1) v += __shfl_xor_sync(0xffffffff, v, o);
        if (lane == 0) wsum[e][w] = v;
    }
    __syncthreads();
    if (tid < NE) vals[tid] = wsum[tid][0] + wsum[tid][1] + wsum[tid][2] + wsum[tid][3];
    __syncthreads();
    if (tid == 0) {
        bool used[NE];
        #pragma unroll
        for (int e = 0; e < NE; e++) used[e] = false;
        for (int h = 0; h < NH; h++) {
            int bi = 0; float bv = -3.4e38f;
            for (int e = 0; e < NE; e++)
                if (!used[e] && vals[e] > bv) { bv = vals[e]; bi = e; }
            used[bi] = true;
            g_selidx[bs*NH + h] = bi;
            g_selval[bs*NH + h] = 1.f / (1.f + expf(-bv));
        }
    }
}

// ---------------- sinusoidal embedding --------------------------------------
__global__ void pemb_kernel()
{
    int i = blockIdx.x;
    int tid = threadIdx.x;
    float pos = (float)i - (float)(SS - 1);
    float cst = -logf(10000.f) / (float)IN;
    for (int j = tid; j < IN/2; j += 256) {
        float dv = expf((float)(2*j) * cst);
        float s, co;
        sincosf(pos * dv, &s, &co);
        g_pemb[(long)i*IN + 2*j]     = s;
        g_pemb[(long)i*IN + 2*j + 1] = co;
    }
}

// ---------------- launch ----------------------------------------------------
static float* symf(const void* sym) { void* p = nullptr; cudaGetSymbolAddress(&p, sym); return (float*)p; }

extern "C" void kernel_launch(void* const* d_in, const int* in_sizes, int n_in,
                              void* d_out, int out_size)
{
    const float* curr  = (const float*)d_in[0];
    const float* attn  = (const float*)d_in[1];
    const float* dtq   = (const float*)d_in[2];
    const float* dtkv  = (const float*)d_in[3];
    const float* oproj = (const float*)d_in[4];
    const float* ptpk  = (const float*)d_in[5];
    const float* sdst  = (const float*)d_in[6];
    const float* scale = (const float*)d_in[7];
    float* out = (float*)d_out;

    float* p_pemb = symf(g_pemb);
    float* p_kpos = symf(g_kpos);
    float* p_q    = symf(g_q);
    float* p_P    = symf(g_P);
    float* p_z    = symf(g_z);
    float* p_cnt  = symf(g_cnt);

    static int smem_set = 0;
    const int FLASH_SMEM = (64*FQW + 64*FQW + 128*FQW)*2 + 64*FQW*4 + 512*4;
    if (!smem_set) {
        cudaFuncSetAttribute(flash_kernel,
            cudaFuncAttributeMaxDynamicSharedMemorySize, FLASH_SMEM);
        cudaFuncSetAttribute(tgemm<0>,
            cudaFuncAttributeMaxDynamicSharedMemorySize, TG_SMEM);
        cudaFuncSetAttribute(tgemm<1>,
            cudaFuncAttributeMaxDynamicSharedMemorySize, TG_SMEM);
        cudaFuncSetAttribute(qexp_kernel,
            cudaFuncAttributeMaxDynamicSharedMemorySize, QX_SMEM);
        smem_set = 1;
    }

    // expert selection + buckets
    sel_topk_kernel<<<BT, 128>>>(curr, sdst);
    cudaMemsetAsync(p_cnt, 0, NE * sizeof(int));
    qbucket_kernel<<<(BT*NH + 255)/256, 256>>>();

    // bucketed q projection (writes g_q directly, scaled)
    qexp_kernel<<<dim3(1, 32, NE), 256, QX_SMEM>>>(curr, dtq, scale);

    // positional embedding + k_pos = pemb @ pos_to_pk^T * sc
    pemb_kernel<<<RLEN, 256>>>();
    tgemm<1><<<dim3(1, 16, 1), 256, TG_SMEM>>>(p_pemb, ptpk, p_kpos,
        RLEN, PROJ, IN, IN, IN, PROJ, 0, scale, 1, 0, 0, 0, 0, 0);

    // kv = attend_to @ data_to_kv, epilogue splits into g_k (*sc) and g_v
    tgemm<0><<<dim3(2, 32, 1), 256, TG_SMEM>>>(attn, dtkv, nullptr,
        BT, 2*PROJ, IN, IN, 2*PROJ, 2*PROJ, 0, scale, 2, 0, 0, 0, 0, 0);

    // P band = Q @ kpos^T  (only the diagonal band used by shift)
    tgemm<1><<<dim3(9, 8, BB*NH), 256, TG_SMEM>>>(p_q, p_kpos, p_P,
        SS, RLEN, PROJ, PROJ, PROJ, RLEN, 0, scale, 0,
        (long)SS*PROJ, 0, (long)SS*RLEN, 0, 1);

    // fused attention: QK^T + band, softmax, @V, gate, scatter into z
    cudaMemsetAsync(p_z, 0, (size_t)BT*NE*PROJ*sizeof(float));
    flash_kernel<<<dim3(16, BB*NH), 256, FLASH_SMEM>>>();

    // output projection
    tgemm<0><<<dim3(8, 32, 1), 256, TG_SMEM>>>(p_z, oproj, out,
        BT, OUT, NE*PROJ, NE*PROJ, OUT, OUT, 2, scale, 0, 0, 0, 0, 0, 0);
}

// round 9
// speedup vs baseline: 1.7330x; 1.1427x over previous
#include <cuda_runtime.h>
#include <cuda_fp16.h>
#include <math.h>

#define BB 4
#define SS 1024
#define IN 1024
#define OUT 1024
#define NH 8
#define NE 16
#define PROJ 128
#define BT (BB*SS)
#define RLEN (2*SS-1)

// ---------------- scratch ----------------------------------------------------
__device__ float    g_selval[BT*NH];
__device__ int      g_selidx[BT*NH];
__device__ int      g_cnt[NE];
__device__ int      g_list[NE*BT];
__device__ float    g_k   [(size_t)BT*PROJ];
__device__ float    g_v   [(size_t)BT*PROJ];
__device__ float    g_pemb[(size_t)RLEN*IN];
__device__ float    g_kpos[(size_t)RLEN*PROJ];
__device__ unsigned g_kpos_h[(size_t)(RLEN+1)*64];     // fp16x2, 64 u32/row, +1 pad row
__device__ float    g_q   [(size_t)BB*NH*SS*PROJ];
__device__ unsigned g_r   [(size_t)BT*NH*64];          // gated attn out, fp16x2 rows

// ---------------- fp16 helpers ----------------------------------------------
__device__ __forceinline__ unsigned pk2(float x, float y) {
    __half2 h = __floats2half2_rn(x, y);
    return *reinterpret_cast<unsigned*>(&h);
}
__device__ __forceinline__ void mmaf16(float c[4], const unsigned a[4],
                                       const unsigned b[2]) {
    asm volatile(
        "mma.sync.aligned.m16n8k16.row.col.f32.f16.f16.f32 "
        "{%0,%1,%2,%3},{%4,%5,%6,%7},{%8,%9},{%0,%1,%2,%3};"
        : "+f"(c[0]), "+f"(c[1]), "+f"(c[2]), "+f"(c[3])
        : "r"(a[0]), "r"(a[1]), "r"(a[2]), "r"(a[3]),
          "r"(b[0]), "r"(b[1]));
}

// tile geometry for generic GEMM
#define TW 40
#define STG_H (128*TW)
#define TG_SMEM (4*STG_H*2)
#define QX_SMEM (TG_SMEM + 128*4)

// ---------------- fp16 tensor GEMM, double-buffered ------------------------
// TRANSB=0: B row-major KxN. TRANSB=1: B row-major NxK (A @ B^T).
// alphaMode: 0 none, 1 *sqrt(scale), 2 split-kv epilogue (k*sc | v)
template<int TRANSB>
__global__ __launch_bounds__(256, 2)
void tgemm(const float* __restrict__ A, const float* __restrict__ Bm,
           float* __restrict__ C,
           int M, int N, int K, int lda, int ldb, int ldc,
           const float* __restrict__ scalep, int alphaMode)
{
    extern __shared__ half hsm[];
    half* AsBase = hsm;
    half* BsBase = hsm + 2*STG_H;

    const float* Ap = A;
    const float* Bp = Bm;
    float*       Cp = C;
    int m0 = blockIdx.y * 128;
    int n0 = blockIdx.x * 128;

    int tid  = threadIdx.x;
    int wid  = tid >> 5, lane = tid & 31;
    int wm0  = (wid & 1) * 64;
    int wn0  = (wid >> 1) * 32;
    int lg   = lane >> 2;
    int lt   = lane & 3;

    float c[4][4][4];
    #pragma unroll
    for (int i = 0; i < 4; i++)
        #pragma unroll
        for (int j = 0; j < 4; j++)
            #pragma unroll
            for (int q = 0; q < 4; q++) c[i][j][q] = 0.f;

    float4 ra[4];
    float4 rb4[4];
    float  cv[16];

    auto ldA = [&](int k0) {
        #pragma unroll
        for (int i = 0; i < 4; i++) {
            int m  = i * 32 + (tid >> 3);
            int kk = (tid & 7) * 4;
            ra[i] = make_float4(0.f, 0.f, 0.f, 0.f);
            if (m0 + m < M)
                ra[i] = *reinterpret_cast<const float4*>(Ap + (long)(m0 + m) * lda + k0 + kk);
        }
    };
    auto ldB = [&](int k0) {
        if (TRANSB == 0) {
            int n    = tid & 127;
            int kseg = (tid >> 7) * 16;
            const float* src = Bp + (long)(k0 + kseg) * ldb + n0 + n;
            #pragma unroll
            for (int j = 0; j < 16; j++) cv[j] = src[(long)j * ldb];
        } else {
            #pragma unroll
            for (int i = 0; i < 4; i++) {
                int nn = i * 32 + (tid >> 3);
                int kk = (tid & 7) * 4;
                rb4[i] = make_float4(0.f, 0.f, 0.f, 0.f);
                if (n0 + nn < N)
                    rb4[i] = *reinterpret_cast<const float4*>(Bp + (long)(n0 + nn) * ldb + k0 + kk);
            }
        }
    };
    auto stAB = [&](int buf) {
        half* As = AsBase + buf * STG_H;
        half* Bs = BsBase + buf * STG_H;
        #pragma unroll
        for (int i = 0; i < 4; i++) {
            int m  = i * 32 + (tid >> 3);
            int kk = (tid & 7) * 4;
            uint2 w;
            w.x = pk2(ra[i].x, ra[i].y);
            w.y = pk2(ra[i].z, ra[i].w);
            *reinterpret_cast<uint2*>(&As[m * TW + kk]) = w;
        }
        if (TRANSB == 0) {
            int n    = tid & 127;
            int kseg = (tid >> 7) * 16;
            #pragma unroll
            for (int j2 = 0; j2 < 4; j2++) {
                uint2 w;
                w.x = pk2(cv[j2*4+0], cv[j2*4+1]);
                w.y = pk2(cv[j2*4+2], cv[j2*4+3]);
                *reinterpret_cast<uint2*>(&Bs[n * TW + kseg + j2*4]) = w;
            }
        } else {
            #pragma unroll
            for (int i = 0; i < 4; i++) {
                int nn = i * 32 + (tid >> 3);
                int kk = (tid & 7) * 4;
                uint2 w;
                w.x = pk2(rb4[i].x, rb4[i].y);
                w.y = pk2(rb4[i].z, rb4[i].w);
                *reinterpret_cast<uint2*>(&Bs[nn * TW + kk]) = w;
            }
        }
    };
    auto domma = [&](int buf) {
        half* As = AsBase + buf * STG_H;
        half* Bs = BsBase + buf * STG_H;
        #pragma unroll
        for (int ks = 0; ks < 2; ks++) {
            int kb = ks * 16;
            unsigned a[4][4], b[4][2];
            #pragma unroll
            for (int mt = 0; mt < 4; mt++) {
                int r = wm0 + mt * 16 + lg;
                a[mt][0] = *reinterpret_cast<unsigned*>(&As[r * TW + kb + 2*lt]);
                a[mt][1] = *reinterpret_cast<unsigned*>(&As[(r + 8) * TW + kb + 2*lt]);
                a[mt][2] = *reinterpret_cast<unsigned*>(&As[r * TW + kb + 2*lt + 8]);
                a[mt][3] = *reinterpret_cast<unsigned*>(&As[(r + 8) * TW + kb + 2*lt + 8]);
            }
            #pragma unroll
            for (int nt = 0; nt < 4; nt++) {
                int cn = wn0 + nt * 8 + lg;
                b[nt][0] = *reinterpret_cast<unsigned*>(&Bs[cn * TW + kb + 2*lt]);
                b[nt][1] = *reinterpret_cast<unsigned*>(&Bs[cn * TW + kb + 2*lt + 8]);
            }
            #pragma unroll
            for (int mt = 0; mt < 4; mt++)
                #pragma unroll
                for (int nt = 0; nt < 4; nt++)
                    mmaf16(c[mt][nt], a[mt], b[nt]);
        }
    };

    int nk = K / 32;
    ldA(0); ldB(0);
    stAB(0);
    __syncthreads();
    for (int ki = 0; ki < nk; ki++) {
        if (ki + 1 < nk) { ldA((ki + 1) * 32); ldB((ki + 1) * 32); }
        domma(ki & 1);
        if (ki + 1 < nk) {
            stAB((ki + 1) & 1);
            __syncthreads();
        }
    }

    if (alphaMode == 2) {
        float sc = sqrtf(scalep[0]);
        #pragma unroll
        for (int mt = 0; mt < 4; mt++) {
            #pragma unroll
            for (int nt = 0; nt < 4; nt++) {
                #pragma unroll
                for (int ri = 0; ri < 2; ri++) {
                    int r  = m0 + wm0 + mt * 16 + lg + ri * 8;
                    int cc = n0 + wn0 + nt * 8 + 2 * lt;
                    float v0 = c[mt][nt][ri * 2 + 0];
                    float v1 = c[mt][nt][ri * 2 + 1];
                    if (cc < PROJ) {
                        g_k[(size_t)r * PROJ + cc]     = sc * v0;
                        g_k[(size_t)r * PROJ + cc + 1] = sc * v1;
                    } else {
                        g_v[(size_t)r * PROJ + cc - PROJ]     = v0;
                        g_v[(size_t)r * PROJ + cc - PROJ + 1] = v1;
                    }
                }
            }
        }
        return;
    }

    float alpha = (alphaMode == 1) ? sqrtf(scalep[0]) : 1.f;
    #pragma unroll
    for (int mt = 0; mt < 4; mt++) {
        #pragma unroll
        for (int nt = 0; nt < 4; nt++) {
            int r  = m0 + wm0 + mt * 16 + lg;
            int cc = n0 + wn0 + nt * 8 + 2 * lt;
            if (r < M) {
                if (cc     < N) Cp[(long)r * ldc + cc]     = alpha * c[mt][nt][0];
                if (cc + 1 < N) Cp[(long)r * ldc + cc + 1] = alpha * c[mt][nt][1];
            }
            if (r + 8 < M) {
                if (cc     < N) Cp[(long)(r + 8) * ldc + cc]     = alpha * c[mt][nt][2];
                if (cc + 1 < N) Cp[(long)(r + 8) * ldc + cc + 1] = alpha * c[mt][nt][3];
            }
        }
    }
}

// ---------------- expert-bucketed q projection (fp16 MMA) -------------------
__global__ __launch_bounds__(256, 2)
void qexp_kernel(const float* __restrict__ curr, const float* __restrict__ dtq,
                 const float* __restrict__ scalep)
{
    extern __shared__ half hsm[];
    half* AsBase = hsm;
    half* BsBase = hsm + 2*STG_H;
    int*  ent    = (int*)(hsm + 4*STG_H);

    int e   = blockIdx.z;
    int cnt = g_cnt[e];
    int t0  = blockIdx.y * 128;
    if (t0 >= cnt) return;

    int tid  = threadIdx.x;
    if (tid < 128)
        ent[tid] = (t0 + tid < cnt) ? g_list[e * BT + t0 + tid] : -1;
    __syncthreads();

    const float* Bp = dtq + (size_t)e * IN * PROJ;

    int wid  = tid >> 5, lane = tid & 31;
    int wm0  = (wid & 1) * 64;
    int wn0  = (wid >> 1) * 32;
    int lg   = lane >> 2;
    int lt   = lane & 3;

    int tok4[4];
    #pragma unroll
    for (int i = 0; i < 4; i++) {
        int m = i * 32 + (tid >> 3);
        int en = ent[m];
        tok4[i] = (en >= 0) ? (en >> 3) : -1;
    }

    float c[4][4][4];
    #pragma unroll
    for (int i = 0; i < 4; i++)
        #pragma unroll
        for (int j = 0; j < 4; j++)
            #pragma unroll
            for (int q = 0; q < 4; q++) c[i][j][q] = 0.f;

    float4 ra[4];
    float  cv[16];
    auto ldA = [&](int k0) {
        int kk = (tid & 7) * 4;
        #pragma unroll
        for (int i = 0; i < 4; i++) {
            ra[i] = make_float4(0.f, 0.f, 0.f, 0.f);
            if (tok4[i] >= 0)
                ra[i] = *reinterpret_cast<const float4*>(curr + (size_t)tok4[i] * IN + k0 + kk);
        }
    };
    auto ldB = [&](int k0) {
        int n    = tid & 127;
        int kseg = (tid >> 7) * 16;
        const float* src = Bp + (size_t)(k0 + kseg) * PROJ + n;
        #pragma unroll
        for (int j = 0; j < 16; j++) cv[j] = src[(size_t)j * PROJ];
    };
    auto stAB = [&](int buf) {
        half* As = AsBase + buf * STG_H;
        half* Bs = BsBase + buf * STG_H;
        int kk = (tid & 7) * 4;
        #pragma unroll
        for (int i = 0; i < 4; i++) {
            int m = i * 32 + (tid >> 3);
            uint2 w;
            w.x = pk2(ra[i].x, ra[i].y);
            w.y = pk2(ra[i].z, ra[i].w);
            *reinterpret_cast<uint2*>(&As[m * TW + kk]) = w;
        }
        int n    = tid & 127;
        int kseg = (tid >> 7) * 16;
        #pragma unroll
        for (int j2 = 0; j2 < 4; j2++) {
            uint2 w;
            w.x = pk2(cv[j2*4+0], cv[j2*4+1]);
            w.y = pk2(cv[j2*4+2], cv[j2*4+3]);
            *reinterpret_cast<uint2*>(&Bs[n * TW + kseg + j2*4]) = w;
        }
    };
    auto domma = [&](int buf) {
        half* As = AsBase + buf * STG_H;
        half* Bs = BsBase + buf * STG_H;
        #pragma unroll
        for (int ks = 0; ks < 2; ks++) {
            int kb = ks * 16;
            unsigned a[4][4], b[4][2];
            #pragma unroll
            for (int mt = 0; mt < 4; mt++) {
                int r = wm0 + mt * 16 + lg;
                a[mt][0] = *reinterpret_cast<unsigned*>(&As[r * TW + kb + 2*lt]);
                a[mt][1] = *reinterpret_cast<unsigned*>(&As[(r + 8) * TW + kb + 2*lt]);
                a[mt][2] = *reinterpret_cast<unsigned*>(&As[r * TW + kb + 2*lt + 8]);
                a[mt][3] = *reinterpret_cast<unsigned*>(&As[(r + 8) * TW + kb + 2*lt + 8]);
            }
            #pragma unroll
            for (int nt = 0; nt < 4; nt++) {
                int cn = wn0 + nt * 8 + lg;
                b[nt][0] = *reinterpret_cast<unsigned*>(&Bs[cn * TW + kb + 2*lt]);
                b[nt][1] = *reinterpret_cast<unsigned*>(&Bs[cn * TW + kb + 2*lt + 8]);
            }
            #pragma unroll
            for (int mt = 0; mt < 4; mt++)
                #pragma unroll
                for (int nt = 0; nt < 4; nt++)
                    mmaf16(c[mt][nt], a[mt], b[nt]);
        }
    };

    ldA(0); ldB(0);
    stAB(0);
    __syncthreads();
    for (int ki = 0; ki < 32; ki++) {
        if (ki + 1 < 32) { ldA((ki + 1) * 32); ldB((ki + 1) * 32); }
        domma(ki & 1);
        if (ki + 1 < 32) { stAB((ki + 1) & 1); __syncthreads(); }
    }

    float alpha = sqrtf(scalep[0]);
    #pragma unroll
    for (int mt = 0; mt < 4; mt++) {
        #pragma unroll
        for (int ri = 0; ri < 2; ri++) {
            int rl = wm0 + mt * 16 + lg + ri * 8;
            int en = ent[rl];
            if (en < 0) continue;
            int token = en >> 3, h = en & 7;
            int b = token >> 10, s = token & 1023;
            float* dst = g_q + ((size_t)((b * NH + h) * SS + s)) * PROJ;
            #pragma unroll
            for (int nt = 0; nt < 4; nt++) {
                int cc = wn0 + nt * 8 + 2 * lt;
                dst[cc]     = alpha * c[mt][nt][ri * 2 + 0];
                dst[cc + 1] = alpha * c[mt][nt][ri * 2 + 1];
            }
        }
    }
}

// ---------------- bucketed output projection (fp16 MMA, atomic add) ---------
#define FQW 136
__global__ __launch_bounds__(256, 2)
void obucket_kernel(const float* __restrict__ oproj, float* __restrict__ out)
{
    extern __shared__ half hsm[];
    half* As = hsm;                       // 128 x 136
    half* Bs = hsm + 128*FQW;             // 128 x 136
    int*  ent = (int*)(hsm + 2*128*FQW);

    int e   = blockIdx.z;
    int cnt = g_cnt[e];
    int t0  = blockIdx.y * 128;
    if (t0 >= cnt) return;
    int n0  = blockIdx.x * 128;

    int tid = threadIdx.x;
    if (tid < 128)
        ent[tid] = (t0 + tid < cnt) ? g_list[e * BT + t0 + tid] : -1;
    __syncthreads();

    // A: g_r rows (already fp16)
    #pragma unroll
    for (int it = 0; it < 8; it++) {
        int lin = it * 256 + tid;
        int r = lin >> 4, c4 = lin & 15;
        int en = ent[r];
        uint4 v = make_uint4(0, 0, 0, 0);
        if (en >= 0)
            v = reinterpret_cast<const uint4*>(g_r)[(size_t)en * 16 + c4];
        *reinterpret_cast<uint4*>(&As[r * FQW + c4 * 8]) = v;
    }
    // B: oproj[e][k][n0+n] fp32 -> half, layout Bs[n][k]
    {
        int n    = tid & 127;
        int kseg = (tid >> 7) * 64;
        const float* src = oproj + (size_t)e * PROJ * OUT + (size_t)kseg * OUT + n0 + n;
        #pragma unroll
        for (int j2 = 0; j2 < 32; j2++) {
            float v0 = src[(size_t)(2*j2) * OUT];
            float v1 = src[(size_t)(2*j2+1) * OUT];
            *reinterpret_cast<unsigned*>(&Bs[n * FQW + kseg + 2*j2]) = pk2(v0, v1);
        }
    }
    __syncthreads();

    int wid = tid >> 5, lane = tid & 31;
    int wm0 = (wid & 1) * 64;
    int wn0 = (wid >> 1) * 32;
    int lg  = lane >> 2;
    int lt  = lane & 3;

    float c[4][4][4];
    #pragma unroll
    for (int i = 0; i < 4; i++)
        #pragma unroll
        for (int j = 0; j < 4; j++)
            #pragma unroll
            for (int q = 0; q < 4; q++) c[i][j][q] = 0.f;

    #pragma unroll
    for (int ks = 0; ks < 8; ks++) {
        int kb = ks * 16;
        unsigned a[4][4], b[4][2];
        #pragma unroll
        for (int mt = 0; mt < 4; mt++) {
            int r = wm0 + mt * 16 + lg;
            a[mt][0] = *reinterpret_cast<unsigned*>(&As[r * FQW + kb + 2*lt]);
            a[mt][1] = *reinterpret_cast<unsigned*>(&As[(r + 8) * FQW + kb + 2*lt]);
            a[mt][2] = *reinterpret_cast<unsigned*>(&As[r * FQW + kb + 2*lt + 8]);
            a[mt][3] = *reinterpret_cast<unsigned*>(&As[(r + 8) * FQW + kb + 2*lt + 8]);
        }
        #pragma unroll
        for (int nt = 0; nt < 4; nt++) {
            int cn = wn0 + nt * 8 + lg;
            b[nt][0] = *reinterpret_cast<unsigned*>(&Bs[cn * FQW + kb + 2*lt]);
            b[nt][1] = *reinterpret_cast<unsigned*>(&Bs[cn * FQW + kb + 2*lt + 8]);
        }
        #pragma unroll
        for (int mt = 0; mt < 4; mt++)
            #pragma unroll
            for (int nt = 0; nt < 4; nt++)
                mmaf16(c[mt][nt], a[mt], b[nt]);
    }

    #pragma unroll
    for (int mt = 0; mt < 4; mt++) {
        #pragma unroll
        for (int ri = 0; ri < 2; ri++) {
            int rl = wm0 + mt * 16 + lg + ri * 8;
            int en = ent[rl];
            if (en < 0) continue;
            int token = en >> 3;
            float* orow = out + (size_t)token * OUT;
            #pragma unroll
            for (int nt = 0; nt < 4; nt++) {
                int cc = n0 + wn0 + nt * 8 + 2 * lt;
                atomicAdd(&orow[cc],     c[mt][nt][ri * 2 + 0]);
                atomicAdd(&orow[cc + 1], c[mt][nt][ri * 2 + 1]);
            }
        }
    }
}

// ---------------- bucket build ----------------------------------------------
__global__ void qbucket_kernel()
{
    int i = blockIdx.x * 256 + threadIdx.x;
    if (i >= BT * NH) return;
    int e = g_selidx[i];
    int pos = atomicAdd(&g_cnt[e], 1);
    g_list[e * BT + pos] = i;
}

// ---------------- fused flash attention + relative-position band -------------
#define GW 198
__global__ __launch_bounds__(256)
void flash_kernel()
{
    extern __shared__ char smc[];
    half*     Qs   = (half*)smc;                        // 64 x 136
    half*     Ps   = Qs + 64*FQW;                       // 64 x 136
    half*     Kt   = Ps + 64*FQW;                       // 128 x 136
    half*     Kp   = Kt + 128*FQW;                      // 192 x 136 (kpos window)
    unsigned* Vt2  = (unsigned*)(Kp + 192*FQW);         // 64 x 136 (paired V)
    float*    Gs   = (float*)(Vt2 + 64*FQW);            // 64 x 198
    float*    redm = Gs + 64*GW;                        // 256
    float*    reds = redm + 256;                        // 256

    int zh = blockIdx.y;
    int b  = zh >> 3, h = zh & 7;
    int s0 = blockIdx.x * 64;
    int tid = threadIdx.x;
    int wid = tid >> 5, lane = tid & 31;
    int lg = lane >> 2, lt = lane & 3;
    int wm0 = (wid & 1) * 32;
    int wn0 = (wid >> 1) * 32;
    // G warp tiling (64 x 192 cooperative GEMM)
    int gm = (wid & 3) * 16;
    int gn = (wid >> 2) * 96;

    // Q tile 64x128 -> half
    {
        const float* qbase = g_q + (size_t)(zh * SS + s0) * PROJ;
        #pragma unroll
        for (int it = 0; it < 8; it++) {
            int lin = it * 256 + tid;
            int r = lin >> 5, cc = (lin & 31) * 4;
            float4 v = *reinterpret_cast<const float4*>(qbase + (size_t)r * PROJ + cc);
            uint2 w; w.x = pk2(v.x, v.y); w.y = pk2(v.z, v.w);
            *reinterpret_cast<uint2*>(&Qs[r * FQW + cc]) = w;
        }
    }

    float o[2][4][4];
    float mrow[2][2], lrow[2][2];
    #pragma unroll
    for (int mt = 0; mt < 2; mt++) {
        mrow[mt][0] = mrow[mt][1] = -1e30f;
        lrow[mt][0] = lrow[mt][1] = 0.f;
        #pragma unroll
        for (int nt = 0; nt < 4; nt++)
            #pragma unroll
            for (int q = 0; q < 4; q++) o[mt][nt][q] = 0.f;
    }

    for (int kt = 0; kt < 8; kt++) {
        int t0  = kt * 128;
        int bt0 = b * SS + t0;
        int base = t0 - s0 + 960;   // kpos window origin, in [0, 1856]
        // K tile 128x128 -> half [t][p]
        #pragma unroll
        for (int it = 0; it < 16; it++) {
            int lin = it * 256 + tid;
            int r = lin >> 5, cc = (lin & 31) * 4;
            float4 kv4 = *reinterpret_cast<const float4*>(g_k + (size_t)(bt0 + r) * PROJ + cc);
            uint2 w; w.x = pk2(kv4.x, kv4.y); w.y = pk2(kv4.z, kv4.w);
            *reinterpret_cast<uint2*>(&Kt[r * FQW + cc]) = w;
        }
        // V tile paired
        #pragma unroll
        for (int it = 0; it < 8; it++) {
            int lin = it * 256 + tid;
            int tp = lin >> 5, p0 = (lin & 31) * 4;
            float4 v0 = *reinterpret_cast<const float4*>(g_v + (size_t)(bt0 + 2*tp) * PROJ + p0);
            float4 v1 = *reinterpret_cast<const float4*>(g_v + (size_t)(bt0 + 2*tp + 1) * PROJ + p0);
            uint4 w;
            w.x = pk2(v0.x, v1.x); w.y = pk2(v0.y, v1.y);
            w.z = pk2(v0.z, v1.z); w.w = pk2(v0.w, v1.w);
            *reinterpret_cast<uint4*>(&Vt2[tp * FQW + p0]) = w;
        }
        // kpos window 192 rows (fp16, L2-resident)
        {
            const uint4* kp4 = reinterpret_cast<const uint4*>(g_kpos_h);
            #pragma unroll
            for (int it = 0; it < 12; it++) {
                int lin = it * 256 + tid;
                int w = lin >> 4, c4 = lin & 15;
                uint4 v = kp4[(size_t)(base + w) * 16 + c4];
                *reinterpret_cast<uint4*>(&Kp[w * FQW + c4 * 8]) = v;
            }
        }
        __syncthreads();

        // --- G = Q @ Kp^T (64x192) cooperative, staged to Gs ---
        {
            float gg[12][4];
            #pragma unroll
            for (int nt = 0; nt < 12; nt++)
                #pragma unroll
                for (int q = 0; q < 4; q++) gg[nt][q] = 0.f;
            #pragma unroll
            for (int ks = 0; ks < 8; ks++) {
                int kb = ks * 16;
                unsigned a[4], bf[12][2];
                a[0] = *reinterpret_cast<unsigned*>(&Qs[(gm + lg) * FQW + kb + 2*lt]);
                a[1] = *reinterpret_cast<unsigned*>(&Qs[(gm + 8 + lg) * FQW + kb + 2*lt]);
                a[2] = *reinterpret_cast<unsigned*>(&Qs[(gm + lg) * FQW + kb + 2*lt + 8]);
                a[3] = *reinterpret_cast<unsigned*>(&Qs[(gm + 8 + lg) * FQW + kb + 2*lt + 8]);
                #pragma unroll
                for (int nt = 0; nt < 12; nt++) {
                    int cn = gn + nt * 8 + lg;
                    bf[nt][0] = *reinterpret_cast<unsigned*>(&Kp[cn * FQW + kb + 2*lt]);
                    bf[nt][1] = *reinterpret_cast<unsigned*>(&Kp[cn * FQW + kb + 2*lt + 8]);
                }
                #pragma unroll
                for (int nt = 0; nt < 12; nt++)
                    mmaf16(gg[nt], a, bf[nt]);
            }
            #pragma unroll
            for (int nt = 0; nt < 12; nt++) {
                int col = gn + nt * 8 + 2 * lt;
                *reinterpret_cast<float2*>(&Gs[(gm + lg) * GW + col]) =
                    make_float2(gg[nt][0], gg[nt][1]);
                *reinterpret_cast<float2*>(&Gs[(gm + 8 + lg) * GW + col]) =
                    make_float2(gg[nt][2], gg[nt][3]);
            }
        }

        // --- S = Q K^T ---
        float s_[2][4][4];
        #pragma unroll
        for (int mt = 0; mt < 2; mt++)
            #pragma unroll
            for (int nt = 0; nt < 4; nt++)
                #pragma unroll
                for (int q = 0; q < 4; q++) s_[mt][nt][q] = 0.f;
        #pragma unroll
        for (int ks = 0; ks < 8; ks++) {
            int kb = ks * 16;
            unsigned a[2][4], bf[4][2];
            #pragma unroll
            for (int mt = 0; mt < 2; mt++) {
                int r = wm0 + mt * 16 + lg;
                a[mt][0] = *reinterpret_cast<unsigned*>(&Qs[r * FQW + kb + 2*lt]);
                a[mt][1] = *reinterpret_cast<unsigned*>(&Qs[(r + 8) * FQW + kb + 2*lt]);
                a[mt][2] = *reinterpret_cast<unsigned*>(&Qs[r * FQW + kb + 2*lt + 8]);
                a[mt][3] = *reinterpret_cast<unsigned*>(&Qs[(r + 8) * FQW + kb + 2*lt + 8]);
            }
            #pragma unroll
            for (int nt = 0; nt < 4; nt++) {
                int cn = wn0 + nt * 8 + lg;
                bf[nt][0] = *reinterpret_cast<unsigned*>(&Kt[cn * FQW + kb + 2*lt]);
                bf[nt][1] = *reinterpret_cast<unsigned*>(&Kt[cn * FQW + kb + 2*lt + 8]);
            }
            #pragma unroll
            for (int mt = 0; mt < 2; mt++)
                #pragma unroll
                for (int nt = 0; nt < 4; nt++)
                    mmaf16(s_[mt][nt], a[mt], bf[nt]);
        }
        __syncthreads();   // Gs complete

        // band add: S[i,j] += G[i, j-i+63]
        #pragma unroll
        for (int mt = 0; mt < 2; mt++) {
            #pragma unroll
            for (int ri = 0; ri < 2; ri++) {
                int i = wm0 + mt * 16 + lg + ri * 8;
                const float* grow = Gs + (size_t)i * GW - i + 63;
                #pragma unroll
                for (int nt = 0; nt < 4; nt++) {
                    int j = wn0 + nt * 8 + 2 * lt;
                    s_[mt][nt][ri * 2 + 0] += grow[j];
                    s_[mt][nt][ri * 2 + 1] += grow[j + 1];
                }
            }
        }

        // row max
        #pragma unroll
        for (int mt = 0; mt < 2; mt++) {
            #pragma unroll
            for (int ri = 0; ri < 2; ri++) {
                float v = -1e30f;
                #pragma unroll
                for (int nt = 0; nt < 4; nt++)
                    v = fmaxf(v, fmaxf(s_[mt][nt][ri * 2], s_[mt][nt][ri * 2 + 1]));
                v = fmaxf(v, __shfl_xor_sync(0xffffffff, v, 1));
                v = fmaxf(v, __shfl_xor_sync(0xffffffff, v, 2));
                if (lt == 0) {
                    int rl = wm0 + mt * 16 + lg + ri * 8;
                    redm[rl * 4 + (wid >> 1)] = v;
                }
            }
        }
        __syncthreads();

        float scl[2][2];
        #pragma unroll
        for (int mt = 0; mt < 2; mt++) {
            #pragma unroll
            for (int ri = 0; ri < 2; ri++) {
                int rl = wm0 + mt * 16 + lg + ri * 8;
                float v = fmaxf(fmaxf(redm[rl * 4 + 0], redm[rl * 4 + 1]),
                                fmaxf(redm[rl * 4 + 2], redm[rl * 4 + 3]));
                float mnew = fmaxf(mrow[mt][ri], v);
                scl[mt][ri] = expf(mrow[mt][ri] - mnew);
                mrow[mt][ri] = mnew;
            }
        }

        #pragma unroll
        for (int mt = 0; mt < 2; mt++) {
            #pragma unroll
            for (int ri = 0; ri < 2; ri++) {
                float m = mrow[mt][ri];
                float sum = 0.f;
                int r = wm0 + mt * 16 + lg + ri * 8;
                #pragma unroll
                for (int nt = 0; nt < 4; nt++) {
                    float e0 = expf(s_[mt][nt][ri * 2 + 0] - m);
                    float e1 = expf(s_[mt][nt][ri * 2 + 1] - m);
                    sum += e0 + e1;
                    int c0 = wn0 + nt * 8 + 2 * lt;
                    *reinterpret_cast<unsigned*>(&Ps[r * FQW + c0]) = pk2(e0, e1);
                    o[mt][nt][ri * 2 + 0] *= scl[mt][ri];
                    o[mt][nt][ri * 2 + 1] *= scl[mt][ri];
                }
                sum += __shfl_xor_sync(0xffffffff, sum, 1);
                sum += __shfl_xor_sync(0xffffffff, sum, 2);
                if (lt == 0) reds[r * 4 + (wid >> 1)] = sum;
            }
        }
        __syncthreads();

        #pragma unroll
        for (int mt = 0; mt < 2; mt++) {
            #pragma unroll
            for (int ri = 0; ri < 2; ri++) {
                int rl = wm0 + mt * 16 + lg + ri * 8;
                float ltile = reds[rl * 4 + 0] + reds[rl * 4 + 1]
                            + reds[rl * 4 + 2] + reds[rl * 4 + 3];
                lrow[mt][ri] = lrow[mt][ri] * scl[mt][ri] + ltile;
            }
        }

        // O += P @ V
        #pragma unroll
        for (int ks = 0; ks < 8; ks++) {
            int kb = ks * 16;
            unsigned a[2][4], bf[4][2];
            #pragma unroll
            for (int mt = 0; mt < 2; mt++) {
                int r = wm0 + mt * 16 + lg;
                a[mt][0] = *reinterpret_cast<unsigned*>(&Ps[r * FQW + kb + 2*lt]);
                a[mt][1] = *reinterpret_cast<unsigned*>(&Ps[(r + 8) * FQW + kb + 2*lt]);
                a[mt][2] = *reinterpret_cast<unsigned*>(&Ps[r * FQW + kb + 2*lt + 8]);
                a[mt][3] = *reinterpret_cast<unsigned*>(&Ps[(r + 8) * FQW + kb + 2*lt + 8]);
            }
            #pragma unroll
            for (int nt = 0; nt < 4; nt++) {
                int col = wn0 + nt * 8 + lg;
                bf[nt][0] = Vt2[(kb/2 + lt) * FQW + col];
                bf[nt][1] = Vt2[(kb/2 + lt + 4) * FQW + col];
            }
            #pragma unroll
            for (int mt = 0; mt < 2; mt++)
                #pragma unroll
                for (int nt = 0; nt < 4; nt++)
                    mmaf16(o[mt][nt], a[mt], bf[nt]);
        }
        __syncthreads();
    }

    // epilogue: normalize, gate, write fp16 rows to g_r[(token*NH+h)]
    #pragma unroll
    for (int mt = 0; mt < 2; mt++) {
        #pragma unroll
        for (int ri = 0; ri < 2; ri++) {
            int sglob = s0 + wm0 + mt * 16 + lg + ri * 8;
            int token = b * SS + sglob;
            float g = g_selval[token * NH + h];
            float inv = g / lrow[mt][ri];
            unsigned* rrow = g_r + ((size_t)token * NH + h) * 64;
            #pragma unroll
            for (int nt = 0; nt < 4; nt++) {
                int c0 = wn0 + nt * 8 + 2 * lt;
                rrow[c0 >> 1] = pk2(o[mt][nt][ri * 2 + 0] * inv,
                                    o[mt][nt][ri * 2 + 1] * inv);
            }
        }
    }
}

// ---------------- sel = curr @ sel_dst^T, top-8, sigmoid --------------------
__global__ void sel_topk_kernel(const float* __restrict__ curr,
                                const float* __restrict__ sdst)
{
    __shared__ float srow[IN];
    __shared__ float wsum[NE][4];
    __shared__ float vals[NE];
    int bs = blockIdx.x;
    int tid = threadIdx.x;
    const float* row = curr + (long)bs * IN;
    for (int i = tid; i < IN; i += 128) srow[i] = row[i];
    __syncthreads();

    float acc[NE];
    #pragma unroll
    for (int e = 0; e < NE; e++) acc[e] = 0.f;
    for (int i = tid; i < IN; i += 128) {
        float c = srow[i];
        #pragma unroll
        for (int e = 0; e < NE; e++)
            acc[e] = fmaf(c, sdst[e*IN + i], acc[e]);
    }
    int lane = tid & 31, w = tid >> 5;
    #pragma unroll
    for (int e = 0; e < NE; e++) {
        float v = acc[e];
        #pragma unroll
        for (int o = 16; o > 0; o >>= 1) v += __shfl_xor_sync(0xffffffff, v, o);
        if (lane == 0) wsum[e][w] = v;
    }
    __syncthreads();
    if (tid < NE) vals[tid] = wsum[tid][0] + wsum[tid][1] + wsum[tid][2] + wsum[tid][3];
    __syncthreads();
    if (tid == 0) {
        bool used[NE];
        #pragma unroll
        for (int e = 0; e < NE; e++) used[e] = false;
        for (int h = 0; h < NH; h++) {
            int bi = 0; float bv = -3.4e38f;
            for (int e = 0; e < NE; e++)
                if (!used[e] && vals[e] > bv) { bv = vals[e]; bi = e; }
            used[bi] = true;
            g_selidx[bs*NH + h] = bi;
            g_selval[bs*NH + h] = 1.f / (1.f + expf(-bv));
        }
    }
}

// ---------------- sinusoidal embedding --------------------------------------
__global__ void pemb_kernel()
{
    int i = blockIdx.x;
    int tid = threadIdx.x;
    float pos = (float)i - (float)(SS - 1);
    float cst = -logf(10000.f) / (float)IN;
    for (int j = tid; j < IN/2; j += 256) {
        float dv = expf((float)(2*j) * cst);
        float s, co;
        sincosf(pos * dv, &s, &co);
        g_pemb[(long)i*IN + 2*j]     = s;
        g_pemb[(long)i*IN + 2*j + 1] = co;
    }
}

// ---------------- kpos fp32 -> fp16 (with +1 zero pad row) -------------------
__global__ void kpos2h_kernel()
{
    int idx = blockIdx.x * 256 + threadIdx.x;
    if (idx < RLEN * 64) {
        float2 v = reinterpret_cast<const float2*>(g_kpos)[idx];
        g_kpos_h[idx] = pk2(v.x, v.y);
    } else if (idx < (RLEN + 1) * 64) {
        g_kpos_h[idx] = 0u;
    }
}

// ---------------- launch ----------------------------------------------------
static float* symf(const void* sym) { void* p = nullptr; cudaGetSymbolAddress(&p, sym); return (float*)p; }

extern "C" void kernel_launch(void* const* d_in, const int* in_sizes, int n_in,
                              void* d_out, int out_size)
{
    const float* curr  = (const float*)d_in[0];
    const float* attn  = (const float*)d_in[1];
    const float* dtq   = (const float*)d_in[2];
    const float* dtkv  = (const float*)d_in[3];
    const float* oproj = (const float*)d_in[4];
    const float* ptpk  = (const float*)d_in[5];
    const float* sdst  = (const float*)d_in[6];
    const float* scale = (const float*)d_in[7];
    float* out = (float*)d_out;

    float* p_pemb = symf(g_pemb);
    float* p_kpos = symf(g_kpos);
    float* p_cnt  = symf(g_cnt);

    static int smem_set = 0;
    const int FLASH_SMEM = (64*FQW + 64*FQW + 128*FQW + 192*FQW)*2  // halves
                         + 64*FQW*4                                  // Vt2
                         + 64*GW*4 + 512*4;                          // Gs + red
    const int OB_SMEM = 2*128*FQW*2 + 128*4;
    if (!smem_set) {
        cudaFuncSetAttribute(flash_kernel,
            cudaFuncAttributeMaxDynamicSharedMemorySize, FLASH_SMEM);
        cudaFuncSetAttribute(tgemm<0>,
            cudaFuncAttributeMaxDynamicSharedMemorySize, TG_SMEM);
        cudaFuncSetAttribute(tgemm<1>,
            cudaFuncAttributeMaxDynamicSharedMemorySize, TG_SMEM);
        cudaFuncSetAttribute(qexp_kernel,
            cudaFuncAttributeMaxDynamicSharedMemorySize, QX_SMEM);
        cudaFuncSetAttribute(obucket_kernel,
            cudaFuncAttributeMaxDynamicSharedMemorySize, OB_SMEM);
        smem_set = 1;
    }

    // expert selection + buckets
    sel_topk_kernel<<<BT, 128>>>(curr, sdst);
    cudaMemsetAsync(p_cnt, 0, NE * sizeof(int));
    qbucket_kernel<<<(BT*NH + 255)/256, 256>>>();

    // bucketed q projection (writes g_q directly, scaled)
    qexp_kernel<<<dim3(1, 32, NE), 256, QX_SMEM>>>(curr, dtq, scale);

    // positional embedding + k_pos = pemb @ pos_to_pk^T * sc -> fp16
    pemb_kernel<<<RLEN, 256>>>();
    tgemm<1><<<dim3(1, 16, 1), 256, TG_SMEM>>>(p_pemb, ptpk, p_kpos,
        RLEN, PROJ, IN, IN, IN, PROJ, scale, 1);
    kpos2h_kernel<<<((RLEN+1)*64 + 255)/256, 256>>>();

    // kv = attend_to @ data_to_kv, epilogue splits into g_k (*sc) and g_v
    tgemm<0><<<dim3(2, 32, 1), 256, TG_SMEM>>>(attn, dtkv, nullptr,
        BT, 2*PROJ, IN, IN, 2*PROJ, 2*PROJ, scale, 2);

    // fused attention: QK^T + in-kernel relative-position band, softmax, @V,
    // gate, write fp16 rows
    flash_kernel<<<dim3(16, BB*NH), 256, FLASH_SMEM>>>();

    // bucketed output projection (atomic accumulate over heads)
    cudaMemsetAsync(out, 0, (size_t)BT * OUT * sizeof(float));
    obucket_kernel<<<dim3(8, 32, NE), 256, OB_SMEM>>>(oproj, out);
}

// round 11
// speedup vs baseline: 1.8500x; 1.0675x over previous
#include <cuda_runtime.h>
#include <cuda_fp16.h>
#include <math.h>

#define BB 4
#define SS 1024
#define IN 1024
#define OUT 1024
#define NH 8
#define NE 16
#define PROJ 128
#define BT (BB*SS)
#define RLEN (2*SS-1)

// ---------------- scratch ----------------------------------------------------
__device__ float    g_selval[BT*NH];
__device__ int      g_selidx[BT*NH];
__device__ int      g_cnt[NE];
__device__ int      g_list[NE*BT];
__device__ unsigned g_kh  [(size_t)BT*64];             // K * sc, fp16x2
__device__ unsigned g_vh  [(size_t)BT*64];             // V, fp16x2
__device__ float    g_pemb[(size_t)RLEN*IN];
__device__ unsigned g_kpos_h[(size_t)(RLEN+1)*64];     // kpos * sc, fp16x2 (+pad row)
__device__ unsigned g_qh  [(size_t)BB*NH*SS*64];       // Q * sc, fp16x2
__device__ unsigned g_r   [(size_t)BT*NH*64];          // gated attn out, fp16x2

// ---------------- fp16 helpers ----------------------------------------------
__device__ __forceinline__ unsigned pk2(float x, float y) {
    __half2 h = __floats2half2_rn(x, y);
    return *reinterpret_cast<unsigned*>(&h);
}
__device__ __forceinline__ void mmaf16(float c[4], const unsigned a[4],
                                       const unsigned b[2]) {
    asm volatile(
        "mma.sync.aligned.m16n8k16.row.col.f32.f16.f16.f32 "
        "{%0,%1,%2,%3},{%4,%5,%6,%7},{%8,%9},{%0,%1,%2,%3};"
        : "+f"(c[0]), "+f"(c[1]), "+f"(c[2]), "+f"(c[3])
        : "r"(a[0]), "r"(a[1]), "r"(a[2]), "r"(a[3]),
          "r"(b[0]), "r"(b[1]));
}

// tile geometry for generic GEMM
#define TW 40
#define STG_H (128*TW)
#define TG_SMEM (4*STG_H*2)
#define QX_SMEM (TG_SMEM + 128*4)

// ---------------- fp16 tensor GEMM, double-buffered ------------------------
// TRANSB=0: B row-major KxN. TRANSB=1: B row-major NxK (A @ B^T).
// alphaMode: 0 plain fp32 C, 2 split-kv fp16 epilogue (k*sc | v),
//            3 kpos fp16 epilogue (*sqrt(scale) -> g_kpos_h)
template<int TRANSB>
__global__ __launch_bounds__(256, 2)
void tgemm(const float* __restrict__ A, const float* __restrict__ Bm,
           float* __restrict__ C,
           int M, int N, int K, int lda, int ldb, int ldc,
           const float* __restrict__ scalep, int alphaMode)
{
    extern __shared__ half hsm[];
    half* AsBase = hsm;
    half* BsBase = hsm + 2*STG_H;

    const float* Ap = A;
    const float* Bp = Bm;
    float*       Cp = C;
    int m0 = blockIdx.y * 128;
    int n0 = blockIdx.x * 128;

    int tid  = threadIdx.x;
    int wid  = tid >> 5, lane = tid & 31;
    int wm0  = (wid & 1) * 64;
    int wn0  = (wid >> 1) * 32;
    int lg   = lane >> 2;
    int lt   = lane & 3;

    float c[4][4][4];
    #pragma unroll
    for (int i = 0; i < 4; i++)
        #pragma unroll
        for (int j = 0; j < 4; j++)
            #pragma unroll
            for (int q = 0; q < 4; q++) c[i][j][q] = 0.f;

    float4 ra[4];
    float4 rb4[4];
    float  cv[16];

    auto ldA = [&](int k0) {
        #pragma unroll
        for (int i = 0; i < 4; i++) {
            int m  = i * 32 + (tid >> 3);
            int kk = (tid & 7) * 4;
            ra[i] = make_float4(0.f, 0.f, 0.f, 0.f);
            if (m0 + m < M)
                ra[i] = *reinterpret_cast<const float4*>(Ap + (long)(m0 + m) * lda + k0 + kk);
        }
    };
    auto ldB = [&](int k0) {
        if (TRANSB == 0) {
            int n    = tid & 127;
            int kseg = (tid >> 7) * 16;
            const float* src = Bp + (long)(k0 + kseg) * ldb + n0 + n;
            #pragma unroll
            for (int j = 0; j < 16; j++) cv[j] = src[(long)j * ldb];
        } else {
            #pragma unroll
            for (int i = 0; i < 4; i++) {
                int nn = i * 32 + (tid >> 3);
                int kk = (tid & 7) * 4;
                rb4[i] = make_float4(0.f, 0.f, 0.f, 0.f);
                if (n0 + nn < N)
                    rb4[i] = *reinterpret_cast<const float4*>(Bp + (long)(n0 + nn) * ldb + k0 + kk);
            }
        }
    };
    auto stAB = [&](int buf) {
        half* As = AsBase + buf * STG_H;
        half* Bs = BsBase + buf * STG_H;
        #pragma unroll
        for (int i = 0; i < 4; i++) {
            int m  = i * 32 + (tid >> 3);
            int kk = (tid & 7) * 4;
            uint2 w;
            w.x = pk2(ra[i].x, ra[i].y);
            w.y = pk2(ra[i].z, ra[i].w);
            *reinterpret_cast<uint2*>(&As[m * TW + kk]) = w;
        }
        if (TRANSB == 0) {
            int n    = tid & 127;
            int kseg = (tid >> 7) * 16;
            #pragma unroll
            for (int j2 = 0; j2 < 4; j2++) {
                uint2 w;
                w.x = pk2(cv[j2*4+0], cv[j2*4+1]);
                w.y = pk2(cv[j2*4+2], cv[j2*4+3]);
                *reinterpret_cast<uint2*>(&Bs[n * TW + kseg + j2*4]) = w;
            }
        } else {
            #pragma unroll
            for (int i = 0; i < 4; i++) {
                int nn = i * 32 + (tid >> 3);
                int kk = (tid & 7) * 4;
                uint2 w;
                w.x = pk2(rb4[i].x, rb4[i].y);
                w.y = pk2(rb4[i].z, rb4[i].w);
                *reinterpret_cast<uint2*>(&Bs[nn * TW + kk]) = w;
            }
        }
    };
    auto domma = [&](int buf) {
        half* As = AsBase + buf * STG_H;
        half* Bs = BsBase + buf * STG_H;
        #pragma unroll
        for (int ks = 0; ks < 2; ks++) {
            int kb = ks * 16;
            unsigned a[4][4], b[4][2];
            #pragma unroll
            for (int mt = 0; mt < 4; mt++) {
                int r = wm0 + mt * 16 + lg;
                a[mt][0] = *reinterpret_cast<unsigned*>(&As[r * TW + kb + 2*lt]);
                a[mt][1] = *reinterpret_cast<unsigned*>(&As[(r + 8) * TW + kb + 2*lt]);
                a[mt][2] = *reinterpret_cast<unsigned*>(&As[r * TW + kb + 2*lt + 8]);
                a[mt][3] = *reinterpret_cast<unsigned*>(&As[(r + 8) * TW + kb + 2*lt + 8]);
            }
            #pragma unroll
            for (int nt = 0; nt < 4; nt++) {
                int cn = wn0 + nt * 8 + lg;
                b[nt][0] = *reinterpret_cast<unsigned*>(&Bs[cn * TW + kb + 2*lt]);
                b[nt][1] = *reinterpret_cast<unsigned*>(&Bs[cn * TW + kb + 2*lt + 8]);
            }
            #pragma unroll
            for (int mt = 0; mt < 4; mt++)
                #pragma unroll
                for (int nt = 0; nt < 4; nt++)
                    mmaf16(c[mt][nt], a[mt], b[nt]);
        }
    };

    int nk = K / 32;
    ldA(0); ldB(0);
    stAB(0);
    __syncthreads();
    for (int ki = 0; ki < nk; ki++) {
        if (ki + 1 < nk) { ldA((ki + 1) * 32); ldB((ki + 1) * 32); }
        domma(ki & 1);
        if (ki + 1 < nk) {
            stAB((ki + 1) & 1);
            __syncthreads();
        }
    }

    if (alphaMode == 2) {
        // kv epilogue: cc<128 -> g_kh (*sc), else -> g_vh
        float sc = sqrtf(scalep[0]);
        #pragma unroll
        for (int mt = 0; mt < 4; mt++) {
            #pragma unroll
            for (int nt = 0; nt < 4; nt++) {
                #pragma unroll
                for (int ri = 0; ri < 2; ri++) {
                    int r  = m0 + wm0 + mt * 16 + lg + ri * 8;
                    int cc = n0 + wn0 + nt * 8 + 2 * lt;
                    float v0 = c[mt][nt][ri * 2 + 0];
                    float v1 = c[mt][nt][ri * 2 + 1];
                    if (cc < PROJ)
                        g_kh[(size_t)r * 64 + (cc >> 1)] = pk2(sc * v0, sc * v1);
                    else
                        g_vh[(size_t)r * 64 + ((cc - PROJ) >> 1)] = pk2(v0, v1);
                }
            }
        }
        return;
    }
    if (alphaMode == 3) {
        // kpos epilogue: fp16, * sqrt(scale)
        float sc = sqrtf(scalep[0]);
        #pragma unroll
        for (int mt = 0; mt < 4; mt++) {
            #pragma unroll
            for (int ri = 0; ri < 2; ri++) {
                int r = m0 + wm0 + mt * 16 + lg + ri * 8;
                if (r >= M) continue;
                #pragma unroll
                for (int nt = 0; nt < 4; nt++) {
                    int cc = n0 + wn0 + nt * 8 + 2 * lt;
                    g_kpos_h[(size_t)r * 64 + (cc >> 1)] =
                        pk2(sc * c[mt][nt][ri * 2 + 0], sc * c[mt][nt][ri * 2 + 1]);
                }
            }
        }
        return;
    }

    #pragma unroll
    for (int mt = 0; mt < 4; mt++) {
        #pragma unroll
        for (int nt = 0; nt < 4; nt++) {
            int r  = m0 + wm0 + mt * 16 + lg;
            int cc = n0 + wn0 + nt * 8 + 2 * lt;
            if (r < M) {
                if (cc     < N) Cp[(long)r * ldc + cc]     = c[mt][nt][0];
                if (cc + 1 < N) Cp[(long)r * ldc + cc + 1] = c[mt][nt][1];
            }
            if (r + 8 < M) {
                if (cc     < N) Cp[(long)(r + 8) * ldc + cc]     = c[mt][nt][2];
                if (cc + 1 < N) Cp[(long)(r + 8) * ldc + cc + 1] = c[mt][nt][3];
            }
        }
    }
}

// ---------------- expert-bucketed q projection (fp16 MMA, fp16 out) ---------
__global__ __launch_bounds__(256, 2)
void qexp_kernel(const float* __restrict__ curr, const float* __restrict__ dtq,
                 const float* __restrict__ scalep)
{
    extern __shared__ half hsm[];
    half* AsBase = hsm;
    half* BsBase = hsm + 2*STG_H;
    int*  ent    = (int*)(hsm + 4*STG_H);

    int e   = blockIdx.z;
    int cnt = g_cnt[e];
    int t0  = blockIdx.y * 128;
    if (t0 >= cnt) return;

    int tid  = threadIdx.x;
    if (tid < 128)
        ent[tid] = (t0 + tid < cnt) ? g_list[e * BT + t0 + tid] : -1;
    __syncthreads();

    const float* Bp = dtq + (size_t)e * IN * PROJ;

    int wid  = tid >> 5, lane = tid & 31;
    int wm0  = (wid & 1) * 64;
    int wn0  = (wid >> 1) * 32;
    int lg   = lane >> 2;
    int lt   = lane & 3;

    int tok4[4];
    #pragma unroll
    for (int i = 0; i < 4; i++) {
        int m = i * 32 + (tid >> 3);
        int en = ent[m];
        tok4[i] = (en >= 0) ? (en >> 3) : -1;
    }

    float c[4][4][4];
    #pragma unroll
    for (int i = 0; i < 4; i++)
        #pragma unroll
        for (int j = 0; j < 4; j++)
            #pragma unroll
            for (int q = 0; q < 4; q++) c[i][j][q] = 0.f;

    float4 ra[4];
    float  cv[16];
    auto ldA = [&](int k0) {
        int kk = (tid & 7) * 4;
        #pragma unroll
        for (int i = 0; i < 4; i++) {
            ra[i] = make_float4(0.f, 0.f, 0.f, 0.f);
            if (tok4[i] >= 0)
                ra[i] = *reinterpret_cast<const float4*>(curr + (size_t)tok4[i] * IN + k0 + kk);
        }
    };
    auto ldB = [&](int k0) {
        int n    = tid & 127;
        int kseg = (tid >> 7) * 16;
        const float* src = Bp + (size_t)(k0 + kseg) * PROJ + n;
        #pragma unroll
        for (int j = 0; j < 16; j++) cv[j] = src[(size_t)j * PROJ];
    };
    auto stAB = [&](int buf) {
        half* As = AsBase + buf * STG_H;
        half* Bs = BsBase + buf * STG_H;
        int kk = (tid & 7) * 4;
        #pragma unroll
        for (int i = 0; i < 4; i++) {
            int m = i * 32 + (tid >> 3);
            uint2 w;
            w.x = pk2(ra[i].x, ra[i].y);
            w.y = pk2(ra[i].z, ra[i].w);
            *reinterpret_cast<uint2*>(&As[m * TW + kk]) = w;
        }
        int n    = tid & 127;
        int kseg = (tid >> 7) * 16;
        #pragma unroll
        for (int j2 = 0; j2 < 4; j2++) {
            uint2 w;
            w.x = pk2(cv[j2*4+0], cv[j2*4+1]);
            w.y = pk2(cv[j2*4+2], cv[j2*4+3]);
            *reinterpret_cast<uint2*>(&Bs[n * TW + kseg + j2*4]) = w;
        }
    };
    auto domma = [&](int buf) {
        half* As = AsBase + buf * STG_H;
        half* Bs = BsBase + buf * STG_H;
        #pragma unroll
        for (int ks = 0; ks < 2; ks++) {
            int kb = ks * 16;
            unsigned a[4][4], b[4][2];
            #pragma unroll
            for (int mt = 0; mt < 4; mt++) {
                int r = wm0 + mt * 16 + lg;
                a[mt][0] = *reinterpret_cast<unsigned*>(&As[r * TW + kb + 2*lt]);
                a[mt][1] = *reinterpret_cast<unsigned*>(&As[(r + 8) * TW + kb + 2*lt]);
                a[mt][2] = *reinterpret_cast<unsigned*>(&As[r * TW + kb + 2*lt + 8]);
                a[mt][3] = *reinterpret_cast<unsigned*>(&As[(r + 8) * TW + kb + 2*lt + 8]);
            }
            #pragma unroll
            for (int nt = 0; nt < 4; nt++) {
                int cn = wn0 + nt * 8 + lg;
                b[nt][0] = *reinterpret_cast<unsigned*>(&Bs[cn * TW + kb + 2*lt]);
                b[nt][1] = *reinterpret_cast<unsigned*>(&Bs[cn * TW + kb + 2*lt + 8]);
            }
            #pragma unroll
            for (int mt = 0; mt < 4; mt++)
                #pragma unroll
                for (int nt = 0; nt < 4; nt++)
                    mmaf16(c[mt][nt], a[mt], b[nt]);
        }
    };

    ldA(0); ldB(0);
    stAB(0);
    __syncthreads();
    for (int ki = 0; ki < 32; ki++) {
        if (ki + 1 < 32) { ldA((ki + 1) * 32); ldB((ki + 1) * 32); }
        domma(ki & 1);
        if (ki + 1 < 32) { stAB((ki + 1) & 1); __syncthreads(); }
    }

    float alpha = sqrtf(scalep[0]);
    #pragma unroll
    for (int mt = 0; mt < 4; mt++) {
        #pragma unroll
        for (int ri = 0; ri < 2; ri++) {
            int rl = wm0 + mt * 16 + lg + ri * 8;
            int en = ent[rl];
            if (en < 0) continue;
            int token = en >> 3, h = en & 7;
            int b = token >> 10, s = token & 1023;
            unsigned* dst = g_qh + ((size_t)((b * NH + h) * SS + s)) * 64;
            #pragma unroll
            for (int nt = 0; nt < 4; nt++) {
                int cc = wn0 + nt * 8 + 2 * lt;
                dst[cc >> 1] = pk2(alpha * c[mt][nt][ri * 2 + 0],
                                   alpha * c[mt][nt][ri * 2 + 1]);
            }
        }
    }
}

// ---------------- bucketed output projection (fp16 MMA, atomic add) ---------
#define FQW 136
__global__ __launch_bounds__(256, 2)
void obucket_kernel(const float* __restrict__ oproj, float* __restrict__ out)
{
    extern __shared__ half hsm[];
    half* As = hsm;                       // 128 x 136
    half* Bs = hsm + 128*FQW;             // 128 x 136
    int*  ent = (int*)(hsm + 2*128*FQW);

    int e   = blockIdx.z;
    int cnt = g_cnt[e];
    int t0  = blockIdx.y * 128;
    if (t0 >= cnt) return;
    int n0  = blockIdx.x * 128;

    int tid = threadIdx.x;
    if (tid < 128)
        ent[tid] = (t0 + tid < cnt) ? g_list[e * BT + t0 + tid] : -1;
    __syncthreads();

    // A: g_r rows (already fp16)
    #pragma unroll
    for (int it = 0; it < 8; it++) {
        int lin = it * 256 + tid;
        int r = lin >> 4, c4 = lin & 15;
        int en = ent[r];
        uint4 v = make_uint4(0, 0, 0, 0);
        if (en >= 0)
            v = reinterpret_cast<const uint4*>(g_r)[(size_t)en * 16 + c4];
        *reinterpret_cast<uint4*>(&As[r * FQW + c4 * 8]) = v;
    }
    // B: oproj[e][k][n0+n] fp32 -> half, layout Bs[n][k]
    {
        int n    = tid & 127;
        int kseg = (tid >> 7) * 64;
        const float* src = oproj + (size_t)e * PROJ * OUT + (size_t)kseg * OUT + n0 + n;
        #pragma unroll
        for (int j2 = 0; j2 < 32; j2++) {
            float v0 = src[(size_t)(2*j2) * OUT];
            float v1 = src[(size_t)(2*j2+1) * OUT];
            *reinterpret_cast<unsigned*>(&Bs[n * FQW + kseg + 2*j2]) = pk2(v0, v1);
        }
    }
    __syncthreads();

    int wid = tid >> 5, lane = tid & 31;
    int wm0 = (wid & 1) * 64;
    int wn0 = (wid >> 1) * 32;
    int lg  = lane >> 2;
    int lt  = lane & 3;

    float c[4][4][4];
    #pragma unroll
    for (int i = 0; i < 4; i++)
        #pragma unroll
        for (int j = 0; j < 4; j++)
            #pragma unroll
            for (int q = 0; q < 4; q++) c[i][j][q] = 0.f;

    #pragma unroll
    for (int ks = 0; ks < 8; ks++) {
        int kb = ks * 16;
        unsigned a[4][4], b[4][2];
        #pragma unroll
        for (int mt = 0; mt < 4; mt++) {
            int r = wm0 + mt * 16 + lg;
            a[mt][0] = *reinterpret_cast<unsigned*>(&As[r * FQW + kb + 2*lt]);
            a[mt][1] = *reinterpret_cast<unsigned*>(&As[(r + 8) * FQW + kb + 2*lt]);
            a[mt][2] = *reinterpret_cast<unsigned*>(&As[r * FQW + kb + 2*lt + 8]);
            a[mt][3] = *reinterpret_cast<unsigned*>(&As[(r + 8) * FQW + kb + 2*lt + 8]);
        }
        #pragma unroll
        for (int nt = 0; nt < 4; nt++) {
            int cn = wn0 + nt * 8 + lg;
            b[nt][0] = *reinterpret_cast<unsigned*>(&Bs[cn * FQW + kb + 2*lt]);
            b[nt][1] = *reinterpret_cast<unsigned*>(&Bs[cn * FQW + kb + 2*lt + 8]);
        }
        #pragma unroll
        for (int mt = 0; mt < 4; mt++)
            #pragma unroll
            for (int nt = 0; nt < 4; nt++)
                mmaf16(c[mt][nt], a[mt], b[nt]);
    }

    #pragma unroll
    for (int mt = 0; mt < 4; mt++) {
        #pragma unroll
        for (int ri = 0; ri < 2; ri++) {
            int rl = wm0 + mt * 16 + lg + ri * 8;
            int en = ent[rl];
            if (en < 0) continue;
            int token = en >> 3;
            float* orow = out + (size_t)token * OUT;
            #pragma unroll
            for (int nt = 0; nt < 4; nt++) {
                int cc = n0 + wn0 + nt * 8 + 2 * lt;
                atomicAdd(&orow[cc],     c[mt][nt][ri * 2 + 0]);
                atomicAdd(&orow[cc + 1], c[mt][nt][ri * 2 + 1]);
            }
        }
    }
}

// ---------------- bucket build ----------------------------------------------
__global__ void qbucket_kernel()
{
    int i = blockIdx.x * 256 + threadIdx.x;
    if (i >= BT * NH) return;
    int e = g_selidx[i];
    int pos = atomicAdd(&g_cnt[e], 1);
    g_list[e * BT + pos] = i;
}

// ---------------- fused flash attention + relative-position band -------------
#define GW 198
__global__ __launch_bounds__(256)
void flash_kernel()
{
    extern __shared__ char smc[];
    half*     Qs   = (half*)smc;                        // 64 x 136
    half*     Ps   = Qs + 64*FQW;                       // 64 x 136
    half*     Kt   = Ps + 64*FQW;                       // 128 x 136
    half*     Kp   = Kt + 128*FQW;                      // 192 x 136 (kpos window)
    unsigned* Vt2  = (unsigned*)(Kp + 192*FQW);         // 64 x 136 (paired V)
    float*    Gs   = (float*)(Vt2 + 64*FQW);            // 64 x 198
    float*    redm = Gs + 64*GW;                        // 256
    float*    reds = redm + 256;                        // 256

    int zh = blockIdx.y;
    int b  = zh >> 3, h = zh & 7;
    int s0 = blockIdx.x * 64;
    int tid = threadIdx.x;
    int wid = tid >> 5, lane = tid & 31;
    int lg = lane >> 2, lt = lane & 3;
    int wm0 = (wid & 1) * 32;
    int wn0 = (wid >> 1) * 32;
    // G warp tiling (64 x 192 cooperative GEMM)
    int gm = (wid & 3) * 16;
    int gn = (wid >> 2) * 96;

    // Q tile 64x128 halves, direct fp16 copy
    {
        const uint4* qbase = reinterpret_cast<const uint4*>(g_qh + (size_t)(zh * SS + s0) * 64);
        #pragma unroll
        for (int it = 0; it < 4; it++) {
            int lin = it * 256 + tid;
            int r = lin >> 4, c4 = lin & 15;
            *reinterpret_cast<uint4*>(&Qs[r * FQW + c4 * 8]) = qbase[r * 16 + c4];
        }
    }

    float o[2][4][4];
    float mrow[2][2], lrow[2][2];
    #pragma unroll
    for (int mt = 0; mt < 2; mt++) {
        mrow[mt][0] = mrow[mt][1] = -1e30f;
        lrow[mt][0] = lrow[mt][1] = 0.f;
        #pragma unroll
        for (int nt = 0; nt < 4; nt++)
            #pragma unroll
            for (int q = 0; q < 4; q++) o[mt][nt][q] = 0.f;
    }

    for (int kt = 0; kt < 8; kt++) {
        int t0  = kt * 128;
        int bt0 = b * SS + t0;
        int base = t0 - s0 + 960;   // kpos window origin, in [0, 1856]
        // K tile 128x128 halves, direct copy
        {
            const uint4* kbase = reinterpret_cast<const uint4*>(g_kh + (size_t)bt0 * 64);
            #pragma unroll
            for (int it = 0; it < 8; it++) {
                int lin = it * 256 + tid;
                int r = lin >> 4, c4 = lin & 15;
                *reinterpret_cast<uint4*>(&Kt[r * FQW + c4 * 8]) = kbase[r * 16 + c4];
            }
        }
        // V tile paired from fp16: Vt2[tp][p] = {V[2tp][p], V[2tp+1][p]}
        {
            const unsigned* vbase = g_vh + (size_t)bt0 * 64;
            #pragma unroll
            for (int it = 0; it < 8; it++) {
                int lin = it * 256 + tid;
                int tp = lin >> 5, p0 = (lin & 31) * 4;
                uint2 x = *reinterpret_cast<const uint2*>(vbase + (size_t)(2*tp) * 64 + (p0 >> 1));
                uint2 y = *reinterpret_cast<const uint2*>(vbase + (size_t)(2*tp + 1) * 64 + (p0 >> 1));
                uint4 w;
                w.x = __byte_perm(x.x, y.x, 0x5410);
                w.y = __byte_perm(x.x, y.x, 0x7632);
                w.z = __byte_perm(x.y, y.y, 0x5410);
                w.w = __byte_perm(x.y, y.y, 0x7632);
                *reinterpret_cast<uint4*>(&Vt2[tp * FQW + p0]) = w;
            }
        }
        // kpos window 192 rows (fp16, L2-resident)
        {
            const uint4* kp4 = reinterpret_cast<const uint4*>(g_kpos_h);
            #pragma unroll
            for (int it = 0; it < 12; it++) {
                int lin = it * 256 + tid;
                int w = lin >> 4, c4 = lin & 15;
                uint4 v = kp4[(size_t)(base + w) * 16 + c4];
                *reinterpret_cast<uint4*>(&Kp[w * FQW + c4 * 8]) = v;
            }
        }
        __syncthreads();

        // --- G = Q @ Kp^T (64x192) cooperative, staged to Gs ---
        {
            float gg[12][4];
            #pragma unroll
            for (int nt = 0; nt < 12; nt++)
                #pragma unroll
                for (int q = 0; q < 4; q++) gg[nt][q] = 0.f;
            #pragma unroll
            for (int ks = 0; ks < 8; ks++) {
                int kb = ks * 16;
                unsigned a[4], bf[12][2];
                a[0] = *reinterpret_cast<unsigned*>(&Qs[(gm + lg) * FQW + kb + 2*lt]);
                a[1] = *reinterpret_cast<unsigned*>(&Qs[(gm + 8 + lg) * FQW + kb + 2*lt]);
                a[2] = *reinterpret_cast<unsigned*>(&Qs[(gm + lg) * FQW + kb + 2*lt + 8]);
                a[3] = *reinterpret_cast<unsigned*>(&Qs[(gm + 8 + lg) * FQW + kb + 2*lt + 8]);
                #pragma unroll
                for (int nt = 0; nt < 12; nt++) {
                    int cn = gn + nt * 8 + lg;
                    bf[nt][0] = *reinterpret_cast<unsigned*>(&Kp[cn * FQW + kb + 2*lt]);
                    bf[nt][1] = *reinterpret_cast<unsigned*>(&Kp[cn * FQW + kb + 2*lt + 8]);
                }
                #pragma unroll
                for (int nt = 0; nt < 12; nt++)
                    mmaf16(gg[nt], a, bf[nt]);
            }
            #pragma unroll
            for (int nt = 0; nt < 12; nt++) {
                int col = gn + nt * 8 + 2 * lt;
                *reinterpret_cast<float2*>(&Gs[(gm + lg) * GW + col]) =
                    make_float2(gg[nt][0], gg[nt][1]);
                *reinterpret_cast<float2*>(&Gs[(gm + 8 + lg) * GW + col]) =
                    make_float2(gg[nt][2], gg[nt][3]);
            }
        }

        // --- S = Q K^T ---
        float s_[2][4][4];
        #pragma unroll
        for (int mt = 0; mt < 2; mt++)
            #pragma unroll
            for (int nt = 0; nt < 4; nt++)
                #pragma unroll
                for (int q = 0; q < 4; q++) s_[mt][nt][q] = 0.f;
        #pragma unroll
        for (int ks = 0; ks < 8; ks++) {
            int kb = ks * 16;
            unsigned a[2][4], bf[4][2];
            #pragma unroll
            for (int mt = 0; mt < 2; mt++) {
                int r = wm0 + mt * 16 + lg;
                a[mt][0] = *reinterpret_cast<unsigned*>(&Qs[r * FQW + kb + 2*lt]);
                a[mt][1] = *reinterpret_cast<unsigned*>(&Qs[(r + 8) * FQW + kb + 2*lt]);
                a[mt][2] = *reinterpret_cast<unsigned*>(&Qs[r * FQW + kb + 2*lt + 8]);
                a[mt][3] = *reinterpret_cast<unsigned*>(&Qs[(r + 8) * FQW + kb + 2*lt + 8]);
            }
            #pragma unroll
            for (int nt = 0; nt < 4; nt++) {
                int cn = wn0 + nt * 8 + lg;
                bf[nt][0] = *reinterpret_cast<unsigned*>(&Kt[cn * FQW + kb + 2*lt]);
                bf[nt][1] = *reinterpret_cast<unsigned*>(&Kt[cn * FQW + kb + 2*lt + 8]);
            }
            #pragma unroll
            for (int mt = 0; mt < 2; mt++)
                #pragma unroll
                for (int nt = 0; nt < 4; nt++)
                    mmaf16(s_[mt][nt], a[mt], bf[nt]);
        }
        __syncthreads();   // Gs complete

        // band add: S[i,j] += G[i, j-i+63]
        #pragma unroll
        for (int mt = 0; mt < 2; mt++) {
            #pragma unroll
            for (int ri = 0; ri < 2; ri++) {
                int i = wm0 + mt * 16 + lg + ri * 8;
                const float* grow = Gs + (size_t)i * GW - i + 63;
                #pragma unroll
                for (int nt = 0; nt < 4; nt++) {
                    int j = wn0 + nt * 8 + 2 * lt;
                    s_[mt][nt][ri * 2 + 0] += grow[j];
                    s_[mt][nt][ri * 2 + 1] += grow[j + 1];
                }
            }
        }

        // row max
        #pragma unroll
        for (int mt = 0; mt < 2; mt++) {
            #pragma unroll
            for (int ri = 0; ri < 2; ri++) {
                float v = -1e30f;
                #pragma unroll
                for (int nt = 0; nt < 4; nt++)
                    v = fmaxf(v, fmaxf(s_[mt][nt][ri * 2], s_[mt][nt][ri * 2 + 1]));
                v = fmaxf(v, __shfl_xor_sync(0xffffffff, v, 1));
                v = fmaxf(v, __shfl_xor_sync(0xffffffff, v, 2));
                if (lt == 0) {
                    int rl = wm0 + mt * 16 + lg + ri * 8;
                    redm[rl * 4 + (wid >> 1)] = v;
                }
            }
        }
        __syncthreads();

        float scl[2][2];
        #pragma unroll
        for (int mt = 0; mt < 2; mt++) {
            #pragma unroll
            for (int ri = 0; ri < 2; ri++) {
                int rl = wm0 + mt * 16 + lg + ri * 8;
                float v = fmaxf(fmaxf(redm[rl * 4 + 0], redm[rl * 4 + 1]),
                                fmaxf(redm[rl * 4 + 2], redm[rl * 4 + 3]));
                float mnew = fmaxf(mrow[mt][ri], v);
                scl[mt][ri] = expf(mrow[mt][ri] - mnew);
                mrow[mt][ri] = mnew;
            }
        }

        #pragma unroll
        for (int mt = 0; mt < 2; mt++) {
            #pragma unroll
            for (int ri = 0; ri < 2; ri++) {
                float m = mrow[mt][ri];
                float sum = 0.f;
                int r = wm0 + mt * 16 + lg + ri * 8;
                #pragma unroll
                for (int nt = 0; nt < 4; nt++) {
                    float e0 = expf(s_[mt][nt][ri * 2 + 0] - m);
                    float e1 = expf(s_[mt][nt][ri * 2 + 1] - m);
                    sum += e0 + e1;
                    int c0 = wn0 + nt * 8 + 2 * lt;
                    *reinterpret_cast<unsigned*>(&Ps[r * FQW + c0]) = pk2(e0, e1);
                    o[mt][nt][ri * 2 + 0] *= scl[mt][ri];
                    o[mt][nt][ri * 2 + 1] *= scl[mt][ri];
                }
                sum += __shfl_xor_sync(0xffffffff, sum, 1);
                sum += __shfl_xor_sync(0xffffffff, sum, 2);
                if (lt == 0) reds[r * 4 + (wid >> 1)] = sum;
            }
        }
        __syncthreads();

        #pragma unroll
        for (int mt = 0; mt < 2; mt++) {
            #pragma unroll
            for (int ri = 0; ri < 2; ri++) {
                int rl = wm0 + mt * 16 + lg + ri * 8;
                float ltile = reds[rl * 4 + 0] + reds[rl * 4 + 1]
                            + reds[rl * 4 + 2] + reds[rl * 4 + 3];
                lrow[mt][ri] = lrow[mt][ri] * scl[mt][ri] + ltile;
            }
        }

        // O += P @ V
        #pragma unroll
        for (int ks = 0; ks < 8; ks++) {
            int kb = ks * 16;
            unsigned a[2][4], bf[4][2];
            #pragma unroll
            for (int mt = 0; mt < 2; mt++) {
                int r = wm0 + mt * 16 + lg;
                a[mt][0] = *reinterpret_cast<unsigned*>(&Ps[r * FQW + kb + 2*lt]);
                a[mt][1] = *reinterpret_cast<unsigned*>(&Ps[(r + 8) * FQW + kb + 2*lt]);
                a[mt][2] = *reinterpret_cast<unsigned*>(&Ps[r * FQW + kb + 2*lt + 8]);
                a[mt][3] = *reinterpret_cast<unsigned*>(&Ps[(r + 8) * FQW + kb + 2*lt + 8]);
            }
            #pragma unroll
            for (int nt = 0; nt < 4; nt++) {
                int col = wn0 + nt * 8 + lg;
                bf[nt][0] = Vt2[(kb/2 + lt) * FQW + col];
                bf[nt][1] = Vt2[(kb/2 + lt + 4) * FQW + col];
            }
            #pragma unroll
            for (int mt = 0; mt < 2; mt++)
                #pragma unroll
                for (int nt = 0; nt < 4; nt++)
                    mmaf16(o[mt][nt], a[mt], bf[nt]);
        }
        __syncthreads();
    }

    // epilogue: normalize, gate, write fp16 rows to g_r[(token*NH+h)]
    #pragma unroll
    for (int mt = 0; mt < 2; mt++) {
        #pragma unroll
        for (int ri = 0; ri < 2; ri++) {
            int sglob = s0 + wm0 + mt * 16 + lg + ri * 8;
            int token = b * SS + sglob;
            float g = g_selval[token * NH + h];
            float inv = g / lrow[mt][ri];
            unsigned* rrow = g_r + ((size_t)token * NH + h) * 64;
            #pragma unroll
            for (int nt = 0; nt < 4; nt++) {
                int c0 = wn0 + nt * 8 + 2 * lt;
                rrow[c0 >> 1] = pk2(o[mt][nt][ri * 2 + 0] * inv,
                                    o[mt][nt][ri * 2 + 1] * inv);
            }
        }
    }
}

// ---------------- sel = curr @ sel_dst^T, top-8, sigmoid --------------------
__global__ void sel_topk_kernel(const float* __restrict__ curr,
                                const float* __restrict__ sdst)
{
    __shared__ float srow[IN];
    __shared__ float wsum[NE][4];
    __shared__ float vals[NE];
    int bs = blockIdx.x;
    int tid = threadIdx.x;
    const float* row = curr + (long)bs * IN;
    for (int i = tid; i < IN; i += 128) srow[i] = row[i];
    __syncthreads();

    float acc[NE];
    #pragma unroll
    for (int e = 0; e < NE; e++) acc[e] = 0.f;
    for (int i = tid; i < IN; i += 128) {
        float c = srow[i];
        #pragma unroll
        for (int e = 0; e < NE; e++)
            acc[e] = fmaf(c, sdst[e*IN + i], acc[e]);
    }
    int lane = tid & 31, w = tid >> 5;
    #pragma unroll
    for (int e = 0; e < NE; e++) {
        float v = acc[e];
        #pragma unroll
        for (int o = 16; o > 0; o >>= 1) v += __shfl_xor_sync(0xffffffff, v, o);
        if (lane == 0) wsum[e][w] = v;
    }
    __syncthreads();
    if (tid < NE) vals[tid] = wsum[tid][0] + wsum[tid][1] + wsum[tid][2] + wsum[tid][3];
    __syncthreads();
    if (tid == 0) {
        bool used[NE];
        #pragma unroll
        for (int e = 0; e < NE; e++) used[e] = false;
        for (int h = 0; h < NH; h++) {
            int bi = 0; float bv = -3.4e38f;
            for (int e = 0; e < NE; e++)
                if (!used[e] && vals[e] > bv) { bv = vals[e]; bi = e; }
            used[bi] = true;
            g_selidx[bs*NH + h] = bi;
            g_selval[bs*NH + h] = 1.f / (1.f + expf(-bv));
        }
    }
}

// ---------------- sinusoidal embedding --------------------------------------
__global__ void pemb_kernel()
{
    int i = blockIdx.x;
    int tid = threadIdx.x;
    float pos = (float)i - (float)(SS - 1);
    float cst = -logf(10000.f) / (float)IN;
    for (int j = tid; j < IN/2; j += 256) {
        float dv = expf((float)(2*j) * cst);
        float s, co;
        sincosf(pos * dv, &s, &co);
        g_pemb[(long)i*IN + 2*j]     = s;
        g_pemb[(long)i*IN + 2*j + 1] = co;
    }
}

// ---------------- launch ----------------------------------------------------
static char* symc(const void* sym) { void* p = nullptr; cudaGetSymbolAddress(&p, sym); return (char*)p; }

extern "C" void kernel_launch(void* const* d_in, const int* in_sizes, int n_in,
                              void* d_out, int out_size)
{
    const float* curr  = (const float*)d_in[0];
    const float* attn  = (const float*)d_in[1];
    const float* dtq   = (const float*)d_in[2];
    const float* dtkv  = (const float*)d_in[3];
    const float* oproj = (const float*)d_in[4];
    const float* ptpk  = (const float*)d_in[5];
    const float* sdst  = (const float*)d_in[6];
    const float* scale = (const float*)d_in[7];
    float* out = (float*)d_out;

    float* p_pemb   = (float*)symc(g_pemb);
    char*  p_cnt    = symc(g_cnt);
    char*  p_kpos_h = symc(g_kpos_h);

    static int smem_set = 0;
    const int FLASH_SMEM = (64*FQW + 64*FQW + 128*FQW + 192*FQW)*2  // halves
                         + 64*FQW*4                                  // Vt2
                         + 64*GW*4 + 512*4;                          // Gs + red
    const int OB_SMEM = 2*128*FQW*2 + 128*4;
    if (!smem_set) {
        cudaFuncSetAttribute(flash_kernel,
            cudaFuncAttributeMaxDynamicSharedMemorySize, FLASH_SMEM);
        cudaFuncSetAttribute(tgemm<0>,
            cudaFuncAttributeMaxDynamicSharedMemorySize, TG_SMEM);
        cudaFuncSetAttribute(tgemm<1>,
            cudaFuncAttributeMaxDynamicSharedMemorySize, TG_SMEM);
        cudaFuncSetAttribute(qexp_kernel,
            cudaFuncAttributeMaxDynamicSharedMemorySize, QX_SMEM);
        cudaFuncSetAttribute(obucket_kernel,
            cudaFuncAttributeMaxDynamicSharedMemorySize, OB_SMEM);
        smem_set = 1;
    }

    // expert selection + buckets
    sel_topk_kernel<<<BT, 128>>>(curr, sdst);
    cudaMemsetAsync(p_cnt, 0, NE * sizeof(int));
    qbucket_kernel<<<(BT*NH + 255)/256, 256>>>();

    // bucketed q projection (writes g_qh fp16, scaled)
    qexp_kernel<<<dim3(1, 32, NE), 256, QX_SMEM>>>(curr, dtq, scale);

    // positional embedding + k_pos = pemb @ pos_to_pk^T * sc -> fp16 direct
    pemb_kernel<<<RLEN, 256>>>();
    cudaMemsetAsync(p_kpos_h + (size_t)RLEN * 64 * 4, 0, 64 * 4);  // pad row
    tgemm<1><<<dim3(1, 16, 1), 256, TG_SMEM>>>(p_pemb, ptpk, nullptr,
        RLEN, PROJ, IN, IN, IN, PROJ, scale, 3);

    // kv = attend_to @ data_to_kv, epilogue -> g_kh (*sc) / g_vh fp16
    tgemm<0><<<dim3(2, 32, 1), 256, TG_SMEM>>>(attn, dtkv, nullptr,
        BT, 2*PROJ, IN, IN, 2*PROJ, 2*PROJ, scale, 2);

    // fused attention: QK^T + in-kernel relative-position band, softmax, @V,
    // gate, write fp16 rows
    flash_kernel<<<dim3(16, BB*NH), 256, FLASH_SMEM>>>();

    // bucketed output projection (atomic accumulate over heads)
    cudaMemsetAsync(out, 0, (size_t)BT * OUT * sizeof(float));
    obucket_kernel<<<dim3(8, 32, NE), 256, OB_SMEM>>>(oproj, out);
}

// round 12
// speedup vs baseline: 2.1165x; 1.1440x over previous
#include <cuda_runtime.h>
#include <cuda_fp16.h>
#include <math.h>

#define BB 4
#define SS 1024
#define IN 1024
#define OUT 1024
#define NH 8
#define NE 16
#define PROJ 128
#define BT (BB*SS)
#define RLEN (2*SS-1)

// ---------------- scratch ----------------------------------------------------
__device__ float    g_selval[BT*NH];
__device__ int      g_selidx[BT*NH];
__device__ int      g_cnt[NE];
__device__ int      g_list[NE*BT];
__device__ unsigned g_kh  [(size_t)BT*64];             // K * sc, fp16x2
__device__ unsigned g_vh  [(size_t)BT*64];             // V, fp16x2
__device__ float    g_pemb[(size_t)RLEN*IN];
__device__ unsigned g_kpos_h[(size_t)(RLEN+1)*64];     // kpos * sc, fp16x2 (+pad row)
__device__ unsigned g_qh  [(size_t)BB*NH*SS*64];       // Q * sc, fp16x2
__device__ unsigned g_r   [(size_t)BT*NH*64];          // gated attn out, fp16x2

// ---------------- fp16 helpers ----------------------------------------------
__device__ __forceinline__ unsigned pk2(float x, float y) {
    __half2 h = __floats2half2_rn(x, y);
    return *reinterpret_cast<unsigned*>(&h);
}
__device__ __forceinline__ void mmaf16(float c[4], const unsigned a[4],
                                       const unsigned b[2]) {
    asm volatile(
        "mma.sync.aligned.m16n8k16.row.col.f32.f16.f16.f32 "
        "{%0,%1,%2,%3},{%4,%5,%6,%7},{%8,%9},{%0,%1,%2,%3};"
        : "+f"(c[0]), "+f"(c[1]), "+f"(c[2]), "+f"(c[3])
        : "r"(a[0]), "r"(a[1]), "r"(a[2]), "r"(a[3]),
          "r"(b[0]), "r"(b[1]));
}

// tile geometry for generic GEMM
#define TW 40
#define STG_H (128*TW)
#define TG_SMEM (4*STG_H*2)
#define QX_SMEM (TG_SMEM + 128*4)

// ---------------- fp16 tensor GEMM, double-buffered ------------------------
// TRANSB=0: B row-major KxN. TRANSB=1: B row-major NxK (A @ B^T).
// alphaMode: 0 plain fp32 C, 2 split-kv fp16 epilogue (k*sc | v),
//            3 kpos fp16 epilogue (*sqrt(scale) -> g_kpos_h)
template<int TRANSB>
__global__ __launch_bounds__(256, 2)
void tgemm(const float* __restrict__ A, const float* __restrict__ Bm,
           float* __restrict__ C,
           int M, int N, int K, int lda, int ldb, int ldc,
           const float* __restrict__ scalep, int alphaMode)
{
    extern __shared__ half hsm[];
    half* AsBase = hsm;
    half* BsBase = hsm + 2*STG_H;

    const float* Ap = A;
    const float* Bp = Bm;
    float*       Cp = C;
    int m0 = blockIdx.y * 128;
    int n0 = blockIdx.x * 128;

    int tid  = threadIdx.x;
    int wid  = tid >> 5, lane = tid & 31;
    int wm0  = (wid & 1) * 64;
    int wn0  = (wid >> 1) * 32;
    int lg   = lane >> 2;
    int lt   = lane & 3;

    float c[4][4][4];
    #pragma unroll
    for (int i = 0; i < 4; i++)
        #pragma unroll
        for (int j = 0; j < 4; j++)
            #pragma unroll
            for (int q = 0; q < 4; q++) c[i][j][q] = 0.f;

    float4 ra[4];
    float4 rb4[4];
    float  cv[16];

    auto ldA = [&](int k0) {
        #pragma unroll
        for (int i = 0; i < 4; i++) {
            int m  = i * 32 + (tid >> 3);
            int kk = (tid & 7) * 4;
            ra[i] = make_float4(0.f, 0.f, 0.f, 0.f);
            if (m0 + m < M)
                ra[i] = *reinterpret_cast<const float4*>(Ap + (long)(m0 + m) * lda + k0 + kk);
        }
    };
    auto ldB = [&](int k0) {
        if (TRANSB == 0) {
            int n    = tid & 127;
            int kseg = (tid >> 7) * 16;
            const float* src = Bp + (long)(k0 + kseg) * ldb + n0 + n;
            #pragma unroll
            for (int j = 0; j < 16; j++) cv[j] = src[(long)j * ldb];
        } else {
            #pragma unroll
            for (int i = 0; i < 4; i++) {
                int nn = i * 32 + (tid >> 3);
                int kk = (tid & 7) * 4;
                rb4[i] = make_float4(0.f, 0.f, 0.f, 0.f);
                if (n0 + nn < N)
                    rb4[i] = *reinterpret_cast<const float4*>(Bp + (long)(n0 + nn) * ldb + k0 + kk);
            }
        }
    };
    auto stAB = [&](int buf) {
        half* As = AsBase + buf * STG_H;
        half* Bs = BsBase + buf * STG_H;
        #pragma unroll
        for (int i = 0; i < 4; i++) {
            int m  = i * 32 + (tid >> 3);
            int kk = (tid & 7) * 4;
            uint2 w;
            w.x = pk2(ra[i].x, ra[i].y);
            w.y = pk2(ra[i].z, ra[i].w);
            *reinterpret_cast<uint2*>(&As[m * TW + kk]) = w;
        }
        if (TRANSB == 0) {
            int n    = tid & 127;
            int kseg = (tid >> 7) * 16;
            #pragma unroll
            for (int j2 = 0; j2 < 4; j2++) {
                uint2 w;
                w.x = pk2(cv[j2*4+0], cv[j2*4+1]);
                w.y = pk2(cv[j2*4+2], cv[j2*4+3]);
                *reinterpret_cast<uint2*>(&Bs[n * TW + kseg + j2*4]) = w;
            }
        } else {
            #pragma unroll
            for (int i = 0; i < 4; i++) {
                int nn = i * 32 + (tid >> 3);
                int kk = (tid & 7) * 4;
                uint2 w;
                w.x = pk2(rb4[i].x, rb4[i].y);
                w.y = pk2(rb4[i].z, rb4[i].w);
                *reinterpret_cast<uint2*>(&Bs[nn * TW + kk]) = w;
            }
        }
    };
    auto domma = [&](int buf) {
        half* As = AsBase + buf * STG_H;
        half* Bs = BsBase + buf * STG_H;
        #pragma unroll
        for (int ks = 0; ks < 2; ks++) {
            int kb = ks * 16;
            unsigned a[4][4], b[4][2];
            #pragma unroll
            for (int mt = 0; mt < 4; mt++) {
                int r = wm0 + mt * 16 + lg;
                a[mt][0] = *reinterpret_cast<unsigned*>(&As[r * TW + kb + 2*lt]);
                a[mt][1] = *reinterpret_cast<unsigned*>(&As[(r + 8) * TW + kb + 2*lt]);
                a[mt][2] = *reinterpret_cast<unsigned*>(&As[r * TW + kb + 2*lt + 8]);
                a[mt][3] = *reinterpret_cast<unsigned*>(&As[(r + 8) * TW + kb + 2*lt + 8]);
            }
            #pragma unroll
            for (int nt = 0; nt < 4; nt++) {
                int cn = wn0 + nt * 8 + lg;
                b[nt][0] = *reinterpret_cast<unsigned*>(&Bs[cn * TW + kb + 2*lt]);
                b[nt][1] = *reinterpret_cast<unsigned*>(&Bs[cn * TW + kb + 2*lt + 8]);
            }
            #pragma unroll
            for (int mt = 0; mt < 4; mt++)
                #pragma unroll
                for (int nt = 0; nt < 4; nt++)
                    mmaf16(c[mt][nt], a[mt], b[nt]);
        }
    };

    int nk = K / 32;
    ldA(0); ldB(0);
    stAB(0);
    __syncthreads();
    for (int ki = 0; ki < nk; ki++) {
        if (ki + 1 < nk) { ldA((ki + 1) * 32); ldB((ki + 1) * 32); }
        domma(ki & 1);
        if (ki + 1 < nk) {
            stAB((ki + 1) & 1);
            __syncthreads();
        }
    }

    if (alphaMode == 2) {
        float sc = sqrtf(scalep[0]);
        #pragma unroll
        for (int mt = 0; mt < 4; mt++) {
            #pragma unroll
            for (int nt = 0; nt < 4; nt++) {
                #pragma unroll
                for (int ri = 0; ri < 2; ri++) {
                    int r  = m0 + wm0 + mt * 16 + lg + ri * 8;
                    int cc = n0 + wn0 + nt * 8 + 2 * lt;
                    float v0 = c[mt][nt][ri * 2 + 0];
                    float v1 = c[mt][nt][ri * 2 + 1];
                    if (cc < PROJ)
                        g_kh[(size_t)r * 64 + (cc >> 1)] = pk2(sc * v0, sc * v1);
                    else
                        g_vh[(size_t)r * 64 + ((cc - PROJ) >> 1)] = pk2(v0, v1);
                }
            }
        }
        return;
    }
    if (alphaMode == 3) {
        float sc = sqrtf(scalep[0]);
        #pragma unroll
        for (int mt = 0; mt < 4; mt++) {
            #pragma unroll
            for (int ri = 0; ri < 2; ri++) {
                int r = m0 + wm0 + mt * 16 + lg + ri * 8;
                if (r >= M) continue;
                #pragma unroll
                for (int nt = 0; nt < 4; nt++) {
                    int cc = n0 + wn0 + nt * 8 + 2 * lt;
                    g_kpos_h[(size_t)r * 64 + (cc >> 1)] =
                        pk2(sc * c[mt][nt][ri * 2 + 0], sc * c[mt][nt][ri * 2 + 1]);
                }
            }
        }
        return;
    }

    #pragma unroll
    for (int mt = 0; mt < 4; mt++) {
        #pragma unroll
        for (int nt = 0; nt < 4; nt++) {
            int r  = m0 + wm0 + mt * 16 + lg;
            int cc = n0 + wn0 + nt * 8 + 2 * lt;
            if (r < M) {
                if (cc     < N) Cp[(long)r * ldc + cc]     = c[mt][nt][0];
                if (cc + 1 < N) Cp[(long)r * ldc + cc + 1] = c[mt][nt][1];
            }
            if (r + 8 < M) {
                if (cc     < N) Cp[(long)(r + 8) * ldc + cc]     = c[mt][nt][2];
                if (cc + 1 < N) Cp[(long)(r + 8) * ldc + cc + 1] = c[mt][nt][3];
            }
        }
    }
}

// ---------------- expert-bucketed q projection (fp16 MMA, fp16 out) ---------
__global__ __launch_bounds__(256, 2)
void qexp_kernel(const float* __restrict__ curr, const float* __restrict__ dtq,
                 const float* __restrict__ scalep)
{
    extern __shared__ half hsm[];
    half* AsBase = hsm;
    half* BsBase = hsm + 2*STG_H;
    int*  ent    = (int*)(hsm + 4*STG_H);

    int e   = blockIdx.z;
    int cnt = g_cnt[e];
    int t0  = blockIdx.y * 128;
    if (t0 >= cnt) return;

    int tid  = threadIdx.x;
    if (tid < 128)
        ent[tid] = (t0 + tid < cnt) ? g_list[e * BT + t0 + tid] : -1;
    __syncthreads();

    const float* Bp = dtq + (size_t)e * IN * PROJ;

    int wid  = tid >> 5, lane = tid & 31;
    int wm0  = (wid & 1) * 64;
    int wn0  = (wid >> 1) * 32;
    int lg   = lane >> 2;
    int lt   = lane & 3;

    int tok4[4];
    #pragma unroll
    for (int i = 0; i < 4; i++) {
        int m = i * 32 + (tid >> 3);
        int en = ent[m];
        tok4[i] = (en >= 0) ? (en >> 3) : -1;
    }

    float c[4][4][4];
    #pragma unroll
    for (int i = 0; i < 4; i++)
        #pragma unroll
        for (int j = 0; j < 4; j++)
            #pragma unroll
            for (int q = 0; q < 4; q++) c[i][j][q] = 0.f;

    float4 ra[4];
    float  cv[16];
    auto ldA = [&](int k0) {
        int kk = (tid & 7) * 4;
        #pragma unroll
        for (int i = 0; i < 4; i++) {
            ra[i] = make_float4(0.f, 0.f, 0.f, 0.f);
            if (tok4[i] >= 0)
                ra[i] = *reinterpret_cast<const float4*>(curr + (size_t)tok4[i] * IN + k0 + kk);
        }
    };
    auto ldB = [&](int k0) {
        int n    = tid & 127;
        int kseg = (tid >> 7) * 16;
        const float* src = Bp + (size_t)(k0 + kseg) * PROJ + n;
        #pragma unroll
        for (int j = 0; j < 16; j++) cv[j] = src[(size_t)j * PROJ];
    };
    auto stAB = [&](int buf) {
        half* As = AsBase + buf * STG_H;
        half* Bs = BsBase + buf * STG_H;
        int kk = (tid & 7) * 4;
        #pragma unroll
        for (int i = 0; i < 4; i++) {
            int m = i * 32 + (tid >> 3);
            uint2 w;
            w.x = pk2(ra[i].x, ra[i].y);
            w.y = pk2(ra[i].z, ra[i].w);
            *reinterpret_cast<uint2*>(&As[m * TW + kk]) = w;
        }
        int n    = tid & 127;
        int kseg = (tid >> 7) * 16;
        #pragma unroll
        for (int j2 = 0; j2 < 4; j2++) {
            uint2 w;
            w.x = pk2(cv[j2*4+0], cv[j2*4+1]);
            w.y = pk2(cv[j2*4+2], cv[j2*4+3]);
            *reinterpret_cast<uint2*>(&Bs[n * TW + kseg + j2*4]) = w;
        }
    };
    auto domma = [&](int buf) {
        half* As = AsBase + buf * STG_H;
        half* Bs = BsBase + buf * STG_H;
        #pragma unroll
        for (int ks = 0; ks < 2; ks++) {
            int kb = ks * 16;
            unsigned a[4][4], b[4][2];
            #pragma unroll
            for (int mt = 0; mt < 4; mt++) {
                int r = wm0 + mt * 16 + lg;
                a[mt][0] = *reinterpret_cast<unsigned*>(&As[r * TW + kb + 2*lt]);
                a[mt][1] = *reinterpret_cast<unsigned*>(&As[(r + 8) * TW + kb + 2*lt]);
                a[mt][2] = *reinterpret_cast<unsigned*>(&As[r * TW + kb + 2*lt + 8]);
                a[mt][3] = *reinterpret_cast<unsigned*>(&As[(r + 8) * TW + kb + 2*lt + 8]);
            }
            #pragma unroll
            for (int nt = 0; nt < 4; nt++) {
                int cn = wn0 + nt * 8 + lg;
                b[nt][0] = *reinterpret_cast<unsigned*>(&Bs[cn * TW + kb + 2*lt]);
                b[nt][1] = *reinterpret_cast<unsigned*>(&Bs[cn * TW + kb + 2*lt + 8]);
            }
            #pragma unroll
            for (int mt = 0; mt < 4; mt++)
                #pragma unroll
                for (int nt = 0; nt < 4; nt++)
                    mmaf16(c[mt][nt], a[mt], b[nt]);
        }
    };

    ldA(0); ldB(0);
    stAB(0);
    __syncthreads();
    for (int ki = 0; ki < 32; ki++) {
        if (ki + 1 < 32) { ldA((ki + 1) * 32); ldB((ki + 1) * 32); }
        domma(ki & 1);
        if (ki + 1 < 32) { stAB((ki + 1) & 1); __syncthreads(); }
    }

    float alpha = sqrtf(scalep[0]);
    #pragma unroll
    for (int mt = 0; mt < 4; mt++) {
        #pragma unroll
        for (int ri = 0; ri < 2; ri++) {
            int rl = wm0 + mt * 16 + lg + ri * 8;
            int en = ent[rl];
            if (en < 0) continue;
            int token = en >> 3, h = en & 7;
            int b = token >> 10, s = token & 1023;
            unsigned* dst = g_qh + ((size_t)((b * NH + h) * SS + s)) * 64;
            #pragma unroll
            for (int nt = 0; nt < 4; nt++) {
                int cc = wn0 + nt * 8 + 2 * lt;
                dst[cc >> 1] = pk2(alpha * c[mt][nt][ri * 2 + 0],
                                   alpha * c[mt][nt][ri * 2 + 1]);
            }
        }
    }
}

// ---------------- bucketed output projection (fp16 MMA, atomic add) ---------
#define FQW 136
__global__ __launch_bounds__(256, 2)
void obucket_kernel(const float* __restrict__ oproj, float* __restrict__ out)
{
    extern __shared__ half hsm[];
    half* As = hsm;                       // 128 x 136
    half* Bs = hsm + 128*FQW;             // 128 x 136
    int*  ent = (int*)(hsm + 2*128*FQW);

    int e   = blockIdx.z;
    int cnt = g_cnt[e];
    int t0  = blockIdx.y * 128;
    if (t0 >= cnt) return;
    int n0  = blockIdx.x * 128;

    int tid = threadIdx.x;
    if (tid < 128)
        ent[tid] = (t0 + tid < cnt) ? g_list[e * BT + t0 + tid] : -1;
    __syncthreads();

    #pragma unroll
    for (int it = 0; it < 8; it++) {
        int lin = it * 256 + tid;
        int r = lin >> 4, c4 = lin & 15;
        int en = ent[r];
        uint4 v = make_uint4(0, 0, 0, 0);
        if (en >= 0)
            v = reinterpret_cast<const uint4*>(g_r)[(size_t)en * 16 + c4];
        *reinterpret_cast<uint4*>(&As[r * FQW + c4 * 8]) = v;
    }
    {
        int n    = tid & 127;
        int kseg = (tid >> 7) * 64;
        const float* src = oproj + (size_t)e * PROJ * OUT + (size_t)kseg * OUT + n0 + n;
        #pragma unroll
        for (int j2 = 0; j2 < 32; j2++) {
            float v0 = src[(size_t)(2*j2) * OUT];
            float v1 = src[(size_t)(2*j2+1) * OUT];
            *reinterpret_cast<unsigned*>(&Bs[n * FQW + kseg + 2*j2]) = pk2(v0, v1);
        }
    }
    __syncthreads();

    int wid = tid >> 5, lane = tid & 31;
    int wm0 = (wid & 1) * 64;
    int wn0 = (wid >> 1) * 32;
    int lg  = lane >> 2;
    int lt  = lane & 3;

    float c[4][4][4];
    #pragma unroll
    for (int i = 0; i < 4; i++)
        #pragma unroll
        for (int j = 0; j < 4; j++)
            #pragma unroll
            for (int q = 0; q < 4; q++) c[i][j][q] = 0.f;

    #pragma unroll
    for (int ks = 0; ks < 8; ks++) {
        int kb = ks * 16;
        unsigned a[4][4], b[4][2];
        #pragma unroll
        for (int mt = 0; mt < 4; mt++) {
            int r = wm0 + mt * 16 + lg;
            a[mt][0] = *reinterpret_cast<unsigned*>(&As[r * FQW + kb + 2*lt]);
            a[mt][1] = *reinterpret_cast<unsigned*>(&As[(r + 8) * FQW + kb + 2*lt]);
            a[mt][2] = *reinterpret_cast<unsigned*>(&As[r * FQW + kb + 2*lt + 8]);
            a[mt][3] = *reinterpret_cast<unsigned*>(&As[(r + 8) * FQW + kb + 2*lt + 8]);
        }
        #pragma unroll
        for (int nt = 0; nt < 4; nt++) {
            int cn = wn0 + nt * 8 + lg;
            b[nt][0] = *reinterpret_cast<unsigned*>(&Bs[cn * FQW + kb + 2*lt]);
            b[nt][1] = *reinterpret_cast<unsigned*>(&Bs[cn * FQW + kb + 2*lt + 8]);
        }
        #pragma unroll
        for (int mt = 0; mt < 4; mt++)
            #pragma unroll
            for (int nt = 0; nt < 4; nt++)
                mmaf16(c[mt][nt], a[mt], b[nt]);
    }

    #pragma unroll
    for (int mt = 0; mt < 4; mt++) {
        #pragma unroll
        for (int ri = 0; ri < 2; ri++) {
            int rl = wm0 + mt * 16 + lg + ri * 8;
            int en = ent[rl];
            if (en < 0) continue;
            int token = en >> 3;
            float* orow = out + (size_t)token * OUT;
            #pragma unroll
            for (int nt = 0; nt < 4; nt++) {
                int cc = n0 + wn0 + nt * 8 + 2 * lt;
                atomicAdd(&orow[cc],     c[mt][nt][ri * 2 + 0]);
                atomicAdd(&orow[cc + 1], c[mt][nt][ri * 2 + 1]);
            }
        }
    }
}

// ---------------- bucket build ----------------------------------------------
__global__ void qbucket_kernel()
{
    int i = blockIdx.x * 256 + threadIdx.x;
    if (i >= BT * NH) return;
    int e = g_selidx[i];
    int pos = atomicAdd(&g_cnt[e], 1);
    g_list[e * BT + pos] = i;
}

// ---------------- fused flash attention + relative-position band -------------
#define GW 198
__global__ __launch_bounds__(256)
void flash_kernel()
{
    extern __shared__ char smc[];
    half*     Qs   = (half*)smc;                        // 64 x 136
    half*     Ps   = Qs + 64*FQW;                       // 64 x 136
    half*     Kt   = Ps + 64*FQW;                       // 128 x 136
    half*     Kp   = Kt + 128*FQW;                      // 192 x 136 (kpos window)
    unsigned* Vt2  = (unsigned*)(Kp + 192*FQW);         // 64 x 136 (paired V)
    float*    Gs   = (float*)(Vt2 + 64*FQW);            // 64 x 198
    float*    redm = Gs + 64*GW;                        // 256
    float*    reds = redm + 256;                        // 256

    int zh = blockIdx.y;
    int b  = zh >> 3, h = zh & 7;
    int s0 = blockIdx.x * 64;
    int tid = threadIdx.x;
    int wid = tid >> 5, lane = tid & 31;
    int lg = lane >> 2, lt = lane & 3;
    int wm0 = (wid & 1) * 32;
    int wn0 = (wid >> 1) * 32;
    // G warp tiling: 16-row group + 9-tile half-window anchored at ws
    int gm = (wid & 3) * 16;
    int ws = 48 - gm;
    int ghalf = wid >> 2;
    int gc0 = ws + ghalf * 72;

    // Q tile 64x128 halves, direct fp16 copy
    {
        const uint4* qbase = reinterpret_cast<const uint4*>(g_qh + (size_t)(zh * SS + s0) * 64);
        #pragma unroll
        for (int it = 0; it < 4; it++) {
            int lin = it * 256 + tid;
            int r = lin >> 4, c4 = lin & 15;
            *reinterpret_cast<uint4*>(&Qs[r * FQW + c4 * 8]) = qbase[r * 16 + c4];
        }
    }

    float o[2][4][4];
    float mrow[2][2], lrow[2][2];
    #pragma unroll
    for (int mt = 0; mt < 2; mt++) {
        mrow[mt][0] = mrow[mt][1] = -1e30f;
        lrow[mt][0] = lrow[mt][1] = 0.f;
        #pragma unroll
        for (int nt = 0; nt < 4; nt++)
            #pragma unroll
            for (int q = 0; q < 4; q++) o[mt][nt][q] = 0.f;
    }

    for (int kt = 0; kt < 8; kt++) {
        int t0  = kt * 128;
        int bt0 = b * SS + t0;
        int base = t0 - s0 + 960;
        // K tile 128x128 halves, direct copy
        {
            const uint4* kbase = reinterpret_cast<const uint4*>(g_kh + (size_t)bt0 * 64);
            #pragma unroll
            for (int it = 0; it < 8; it++) {
                int lin = it * 256 + tid;
                int r = lin >> 4, c4 = lin & 15;
                *reinterpret_cast<uint4*>(&Kt[r * FQW + c4 * 8]) = kbase[r * 16 + c4];
            }
        }
        // V tile paired from fp16
        {
            const unsigned* vbase = g_vh + (size_t)bt0 * 64;
            #pragma unroll
            for (int it = 0; it < 8; it++) {
                int lin = it * 256 + tid;
                int tp = lin >> 5, p0 = (lin & 31) * 4;
                uint2 x = *reinterpret_cast<const uint2*>(vbase + (size_t)(2*tp) * 64 + (p0 >> 1));
                uint2 y = *reinterpret_cast<const uint2*>(vbase + (size_t)(2*tp + 1) * 64 + (p0 >> 1));
                uint4 w;
                w.x = __byte_perm(x.x, y.x, 0x5410);
                w.y = __byte_perm(x.x, y.x, 0x7632);
                w.z = __byte_perm(x.y, y.y, 0x5410);
                w.w = __byte_perm(x.y, y.y, 0x7632);
                *reinterpret_cast<uint4*>(&Vt2[tp * FQW + p0]) = w;
            }
        }
        // kpos window 192 rows (fp16, L2-resident)
        {
            const uint4* kp4 = reinterpret_cast<const uint4*>(g_kpos_h);
            #pragma unroll
            for (int it = 0; it < 12; it++) {
                int lin = it * 256 + tid;
                int w = lin >> 4, c4 = lin & 15;
                uint4 v = kp4[(size_t)(base + w) * 16 + c4];
                *reinterpret_cast<uint4*>(&Kp[w * FQW + c4 * 8]) = v;
            }
        }
        __syncthreads();

        // --- G = Q @ Kp^T, band-trimmed: 16 rows x 72 cols per warp ---
        {
            float gg[9][4];
            #pragma unroll
            for (int nt = 0; nt < 9; nt++)
                #pragma unroll
                for (int q = 0; q < 4; q++) gg[nt][q] = 0.f;
            #pragma unroll
            for (int ks = 0; ks < 8; ks++) {
                int kb = ks * 16;
                unsigned a[4], bf[9][2];
                a[0] = *reinterpret_cast<unsigned*>(&Qs[(gm + lg) * FQW + kb + 2*lt]);
                a[1] = *reinterpret_cast<unsigned*>(&Qs[(gm + 8 + lg) * FQW + kb + 2*lt]);
                a[2] = *reinterpret_cast<unsigned*>(&Qs[(gm + lg) * FQW + kb + 2*lt + 8]);
                a[3] = *reinterpret_cast<unsigned*>(&Qs[(gm + 8 + lg) * FQW + kb + 2*lt + 8]);
                #pragma unroll
                for (int nt = 0; nt < 9; nt++) {
                    int cn = gc0 + nt * 8 + lg;
                    bf[nt][0] = *reinterpret_cast<unsigned*>(&Kp[cn * FQW + kb + 2*lt]);
                    bf[nt][1] = *reinterpret_cast<unsigned*>(&Kp[cn * FQW + kb + 2*lt + 8]);
                }
                #pragma unroll
                for (int nt = 0; nt < 9; nt++)
                    mmaf16(gg[nt], a, bf[nt]);
            }
            #pragma unroll
            for (int nt = 0; nt < 9; nt++) {
                int col = gc0 + nt * 8 + 2 * lt;
                *reinterpret_cast<float2*>(&Gs[(gm + lg) * GW + col]) =
                    make_float2(gg[nt][0], gg[nt][1]);
                *reinterpret_cast<float2*>(&Gs[(gm + 8 + lg) * GW + col]) =
                    make_float2(gg[nt][2], gg[nt][3]);
            }
        }

        // --- S = Q K^T ---
        float s_[2][4][4];
        #pragma unroll
        for (int mt = 0; mt < 2; mt++)
            #pragma unroll
            for (int nt = 0; nt < 4; nt++)
                #pragma unroll
                for (int q = 0; q < 4; q++) s_[mt][nt][q] = 0.f;
        #pragma unroll
        for (int ks = 0; ks < 8; ks++) {
            int kb = ks * 16;
            unsigned a[2][4], bf[4][2];
            #pragma unroll
            for (int mt = 0; mt < 2; mt++) {
                int r = wm0 + mt * 16 + lg;
                a[mt][0] = *reinterpret_cast<unsigned*>(&Qs[r * FQW + kb + 2*lt]);
                a[mt][1] = *reinterpret_cast<unsigned*>(&Qs[(r + 8) * FQW + kb + 2*lt]);
                a[mt][2] = *reinterpret_cast<unsigned*>(&Qs[r * FQW + kb + 2*lt + 8]);
                a[mt][3] = *reinterpret_cast<unsigned*>(&Qs[(r + 8) * FQW + kb + 2*lt + 8]);
            }
            #pragma unroll
            for (int nt = 0; nt < 4; nt++) {
                int cn = wn0 + nt * 8 + lg;
                bf[nt][0] = *reinterpret_cast<unsigned*>(&Kt[cn * FQW + kb + 2*lt]);
                bf[nt][1] = *reinterpret_cast<unsigned*>(&Kt[cn * FQW + kb + 2*lt + 8]);
            }
            #pragma unroll
            for (int mt = 0; mt < 2; mt++)
                #pragma unroll
                for (int nt = 0; nt < 4; nt++)
                    mmaf16(s_[mt][nt], a[mt], bf[nt]);
        }
        __syncthreads();   // Gs complete

        // band add: S[i,j] += G[i, j-i+63]
        #pragma unroll
        for (int mt = 0; mt < 2; mt++) {
            #pragma unroll
            for (int ri = 0; ri < 2; ri++) {
                int i = wm0 + mt * 16 + lg + ri * 8;
                const float* grow = Gs + (size_t)i * GW - i + 63;
                #pragma unroll
                for (int nt = 0; nt < 4; nt++) {
                    int j = wn0 + nt * 8 + 2 * lt;
                    s_[mt][nt][ri * 2 + 0] += grow[j];
                    s_[mt][nt][ri * 2 + 1] += grow[j + 1];
                }
            }
        }

        // row max
        #pragma unroll
        for (int mt = 0; mt < 2; mt++) {
            #pragma unroll
            for (int ri = 0; ri < 2; ri++) {
                float v = -1e30f;
                #pragma unroll
                for (int nt = 0; nt < 4; nt++)
                    v = fmaxf(v, fmaxf(s_[mt][nt][ri * 2], s_[mt][nt][ri * 2 + 1]));
                v = fmaxf(v, __shfl_xor_sync(0xffffffff, v, 1));
                v = fmaxf(v, __shfl_xor_sync(0xffffffff, v, 2));
                if (lt == 0) {
                    int rl = wm0 + mt * 16 + lg + ri * 8;
                    redm[rl * 4 + (wid >> 1)] = v;
                }
            }
        }
        __syncthreads();

        float scl[2][2];
        #pragma unroll
        for (int mt = 0; mt < 2; mt++) {
            #pragma unroll
            for (int ri = 0; ri < 2; ri++) {
                int rl = wm0 + mt * 16 + lg + ri * 8;
                float v = fmaxf(fmaxf(redm[rl * 4 + 0], redm[rl * 4 + 1]),
                                fmaxf(redm[rl * 4 + 2], redm[rl * 4 + 3]));
                float mnew = fmaxf(mrow[mt][ri], v);
                scl[mt][ri] = expf(mrow[mt][ri] - mnew);
                mrow[mt][ri] = mnew;
            }
        }

        #pragma unroll
        for (int mt = 0; mt < 2; mt++) {
            #pragma unroll
            for (int ri = 0; ri < 2; ri++) {
                float m = mrow[mt][ri];
                float sum = 0.f;
                int r = wm0 + mt * 16 + lg + ri * 8;
                #pragma unroll
                for (int nt = 0; nt < 4; nt++) {
                    float e0 = expf(s_[mt][nt][ri * 2 + 0] - m);
                    float e1 = expf(s_[mt][nt][ri * 2 + 1] - m);
                    sum += e0 + e1;
                    int c0 = wn0 + nt * 8 + 2 * lt;
                    *reinterpret_cast<unsigned*>(&Ps[r * FQW + c0]) = pk2(e0, e1);
                    o[mt][nt][ri * 2 + 0] *= scl[mt][ri];
                    o[mt][nt][ri * 2 + 1] *= scl[mt][ri];
                }
                sum += __shfl_xor_sync(0xffffffff, sum, 1);
                sum += __shfl_xor_sync(0xffffffff, sum, 2);
                if (lt == 0) reds[r * 4 + (wid >> 1)] = sum;
            }
        }
        __syncthreads();

        #pragma unroll
        for (int mt = 0; mt < 2; mt++) {
            #pragma unroll
            for (int ri = 0; ri < 2; ri++) {
                int rl = wm0 + mt * 16 + lg + ri * 8;
                float ltile = reds[rl * 4 + 0] + reds[rl * 4 + 1]
                            + reds[rl * 4 + 2] + reds[rl * 4 + 3];
                lrow[mt][ri] = lrow[mt][ri] * scl[mt][ri] + ltile;
            }
        }

        // O += P @ V
        #pragma unroll
        for (int ks = 0; ks < 8; ks++) {
            int kb = ks * 16;
            unsigned a[2][4], bf[4][2];
            #pragma unroll
            for (int mt = 0; mt < 2; mt++) {
                int r = wm0 + mt * 16 + lg;
                a[mt][0] = *reinterpret_cast<unsigned*>(&Ps[r * FQW + kb + 2*lt]);
                a[mt][1] = *reinterpret_cast<unsigned*>(&Ps[(r + 8) * FQW + kb + 2*lt]);
                a[mt][2] = *reinterpret_cast<unsigned*>(&Ps[r * FQW + kb + 2*lt + 8]);
                a[mt][3] = *reinterpret_cast<unsigned*>(&Ps[(r + 8) * FQW + kb + 2*lt + 8]);
            }
            #pragma unroll
            for (int nt = 0; nt < 4; nt++) {
                int col = wn0 + nt * 8 + lg;
                bf[nt][0] = Vt2[(kb/2 + lt) * FQW + col];
                bf[nt][1] = Vt2[(kb/2 + lt + 4) * FQW + col];
            }
            #pragma unroll
            for (int mt = 0; mt < 2; mt++)
                #pragma unroll
                for (int nt = 0; nt < 4; nt++)
                    mmaf16(o[mt][nt], a[mt], bf[nt]);
        }
        __syncthreads();
    }

    // epilogue: normalize, gate, write fp16 rows to g_r[(token*NH+h)]
    #pragma unroll
    for (int mt = 0; mt < 2; mt++) {
        #pragma unroll
        for (int ri = 0; ri < 2; ri++) {
            int sglob = s0 + wm0 + mt * 16 + lg + ri * 8;
            int token = b * SS + sglob;
            float g = g_selval[token * NH + h];
            float inv = g / lrow[mt][ri];
            unsigned* rrow = g_r + ((size_t)token * NH + h) * 64;
            #pragma unroll
            for (int nt = 0; nt < 4; nt++) {
                int c0 = wn0 + nt * 8 + 2 * lt;
                rrow[c0 >> 1] = pk2(o[mt][nt][ri * 2 + 0] * inv,
                                    o[mt][nt][ri * 2 + 1] * inv);
            }
        }
    }
}

// ---------------- sel = curr @ sel_dst^T, top-8, sigmoid --------------------
__global__ void sel_topk_kernel(const float* __restrict__ curr,
                                const float* __restrict__ sdst)
{
    __shared__ float srow[IN];
    __shared__ float wsum[NE][4];
    __shared__ float vals[NE];
    int bs = blockIdx.x;
    int tid = threadIdx.x;
    const float* row = curr + (long)bs * IN;
    for (int i = tid; i < IN; i += 128) srow[i] = row[i];
    __syncthreads();

    float acc[NE];
    #pragma unroll
    for (int e = 0; e < NE; e++) acc[e] = 0.f;
    for (int i = tid; i < IN; i += 128) {
        float c = srow[i];
        #pragma unroll
        for (int e = 0; e < NE; e++)
            acc[e] = fmaf(c, sdst[e*IN + i], acc[e]);
    }
    int lane = tid & 31, w = tid >> 5;
    #pragma unroll
    for (int e = 0; e < NE; e++) {
        float v = acc[e];
        #pragma unroll
        for (int o = 16; o > 0; o >>= 1) v += __shfl_xor_sync(0xffffffff, v, o);
        if (lane == 0) wsum[e][w] = v;
    }
    __syncthreads();
    if (tid < NE) vals[tid] = wsum[tid][0] + wsum[tid][1] + wsum[tid][2] + wsum[tid][3];
    __syncthreads();
    if (tid == 0) {
        bool used[NE];
        #pragma unroll
        for (int e = 0; e < NE; e++) used[e] = false;
        for (int h = 0; h < NH; h++) {
            int bi = 0; float bv = -3.4e38f;
            for (int e = 0; e < NE; e++)
                if (!used[e] && vals[e] > bv) { bv = vals[e]; bi = e; }
            used[bi] = true;
            g_selidx[bs*NH + h] = bi;
            g_selval[bs*NH + h] = 1.f / (1.f + expf(-bv));
        }
    }
}

// ---------------- sinusoidal embedding --------------------------------------
__global__ void pemb_kernel()
{
    int i = blockIdx.x;
    int tid = threadIdx.x;
    float pos = (float)i - (float)(SS - 1);
    float cst = -logf(10000.f) / (float)IN;
    for (int j = tid; j < IN/2; j += 256) {
        float dv = expf((float)(2*j) * cst);
        float s, co;
        sincosf(pos * dv, &s, &co);
        g_pemb[(long)i*IN + 2*j]     = s;
        g_pemb[(long)i*IN + 2*j + 1] = co;
    }
}

// ---------------- launch ----------------------------------------------------
static char* symc(const void* sym) { void* p = nullptr; cudaGetSymbolAddress(&p, sym); return (char*)p; }

extern "C" void kernel_launch(void* const* d_in, const int* in_sizes, int n_in,
                              void* d_out, int out_size)
{
    const float* curr  = (const float*)d_in[0];
    const float* attn  = (const float*)d_in[1];
    const float* dtq   = (const float*)d_in[2];
    const float* dtkv  = (const float*)d_in[3];
    const float* oproj = (const float*)d_in[4];
    const float* ptpk  = (const float*)d_in[5];
    const float* sdst  = (const float*)d_in[6];
    const float* scale = (const float*)d_in[7];
    float* out = (float*)d_out;

    float* p_pemb   = (float*)symc(g_pemb);
    char*  p_cnt    = symc(g_cnt);
    char*  p_kpos_h = symc(g_kpos_h);

    static int init_done = 0;
    static cudaStream_t s1, s2;
    static cudaEvent_t evRoot, ev1, ev2;
    const int FLASH_SMEM = (64*FQW + 64*FQW + 128*FQW + 192*FQW)*2
                         + 64*FQW*4
                         + 64*GW*4 + 512*4;
    const int OB_SMEM = 2*128*FQW*2 + 128*4;
    if (!init_done) {
        cudaFuncSetAttribute(flash_kernel,
            cudaFuncAttributeMaxDynamicSharedMemorySize, FLASH_SMEM);
        cudaFuncSetAttribute(tgemm<0>,
            cudaFuncAttributeMaxDynamicSharedMemorySize, TG_SMEM);
        cudaFuncSetAttribute(tgemm<1>,
            cudaFuncAttributeMaxDynamicSharedMemorySize, TG_SMEM);
        cudaFuncSetAttribute(qexp_kernel,
            cudaFuncAttributeMaxDynamicSharedMemorySize, QX_SMEM);
        cudaFuncSetAttribute(obucket_kernel,
            cudaFuncAttributeMaxDynamicSharedMemorySize, OB_SMEM);
        cudaStreamCreateWithFlags(&s1, cudaStreamNonBlocking);
        cudaStreamCreateWithFlags(&s2, cudaStreamNonBlocking);
        cudaEventCreateWithFlags(&evRoot, cudaEventDisableTiming);
        cudaEventCreateWithFlags(&ev1, cudaEventDisableTiming);
        cudaEventCreateWithFlags(&ev2, cudaEventDisableTiming);
        init_done = 1;
    }

    // fork
    cudaEventRecord(evRoot, 0);
    cudaStreamWaitEvent(s1, evRoot, 0);
    cudaStreamWaitEvent(s2, evRoot, 0);

    // s1: expert selection + buckets + q projection
    cudaMemsetAsync(p_cnt, 0, NE * sizeof(int), s1);
    sel_topk_kernel<<<BT, 128, 0, s1>>>(curr, sdst);
    qbucket_kernel<<<(BT*NH + 255)/256, 256, 0, s1>>>();
    qexp_kernel<<<dim3(1, 32, NE), 256, QX_SMEM, s1>>>(curr, dtq, scale);
    cudaEventRecord(ev1, s1);

    // s2: positional embedding + kpos + kv
    pemb_kernel<<<RLEN, 256, 0, s2>>>();
    cudaMemsetAsync(p_kpos_h + (size_t)RLEN * 64 * 4, 0, 64 * 4, s2);
    tgemm<1><<<dim3(1, 16, 1), 256, TG_SMEM, s2>>>(p_pemb, ptpk, nullptr,
        RLEN, PROJ, IN, IN, IN, PROJ, scale, 3);
    tgemm<0><<<dim3(2, 32, 1), 256, TG_SMEM, s2>>>(attn, dtkv, nullptr,
        BT, 2*PROJ, IN, IN, 2*PROJ, 2*PROJ, scale, 2);
    cudaEventRecord(ev2, s2);

    // default: zero out while producers run, then join
    cudaMemsetAsync(out, 0, (size_t)BT * OUT * sizeof(float));
    cudaStreamWaitEvent(0, ev1, 0);
    cudaStreamWaitEvent(0, ev2, 0);

    // fused attention
    flash_kernel<<<dim3(16, BB*NH), 256, FLASH_SMEM>>>();

    // bucketed output projection (atomic accumulate over heads)
    obucket_kernel<<<dim3(8, 32, NE), 256, OB_SMEM>>>(oproj, out);
}